// round 1
// baseline (speedup 1.0000x reference)
#include <cuda_runtime.h>

#define BB 4
#define NN 1024
#define FF 256
#define HH 8
#define HIDD 32
#define NF (NN*FF)
#define LALPHA 0.2f

// ---------------- scratch (no allocations allowed) ----------------
__device__ float g_buf  [BB*NN*FF];
__device__ float gs_buf [BB*NN*FF];
__device__ float att_buf[BB*NN*FF];
__device__ float y_buf  [BB*NN*FF];
__device__ float src_buf[BB*NN*HH];
__device__ float dst_buf[BB*NN*HH];
__device__ float den_buf[BB*NN*HH];

// ---------------- GEMM: C[m][o] = sum_k A[m][k]*W[o][k] ----------------
// M = BB*NN = 4096, K = 256, O = 256. Tile 64x64x16, 256 threads, 4x4 micro.
__global__ __launch_bounds__(256) void gemm_nt(const float* __restrict__ A,
                                               const float* __restrict__ W,
                                               float* __restrict__ C) {
    __shared__ float As[16][65];
    __shared__ float Bs[16][65];
    const int m0 = blockIdx.y * 64;
    const int o0 = blockIdx.x * 64;
    const int tx = threadIdx.x & 15;
    const int ty = threadIdx.x >> 4;
    float acc[4][4] = {};
    for (int k0 = 0; k0 < 256; k0 += 16) {
        const int c = threadIdx.x & 15;
        const int r = threadIdx.x >> 4;
        #pragma unroll
        for (int rr = 0; rr < 64; rr += 16) {
            As[c][r + rr] = A[(m0 + r + rr) * 256 + k0 + c];
            Bs[c][r + rr] = W[(o0 + r + rr) * 256 + k0 + c];
        }
        __syncthreads();
        #pragma unroll
        for (int kk = 0; kk < 16; kk++) {
            float ar[4], br[4];
            #pragma unroll
            for (int i = 0; i < 4; i++) ar[i] = As[kk][ty * 4 + i];
            #pragma unroll
            for (int i = 0; i < 4; i++) br[i] = Bs[kk][tx * 4 + i];
            #pragma unroll
            for (int a = 0; a < 4; a++)
                #pragma unroll
                for (int b = 0; b < 4; b++)
                    acc[a][b] = fmaf(ar[a], br[b], acc[a][b]);
        }
        __syncthreads();
    }
    #pragma unroll
    for (int a = 0; a < 4; a++)
        #pragma unroll
        for (int b = 0; b < 4; b++)
            C[(m0 + ty * 4 + a) * 256 + o0 + tx * 4 + b] = acc[a][b];
}

// ---------------- src/dst projections: one warp per (b,n) row ----------------
__global__ __launch_bounds__(256) void srcdst_k(const float* __restrict__ g,
                                                const float* __restrict__ a,
                                                float* __restrict__ src,
                                                float* __restrict__ dst) {
    const int row  = blockIdx.x * 8 + threadIdx.y;   // 0..4095
    const int lane = threadIdx.x;
    const float as = a[lane];
    const float ad = a[32 + lane];
    const float* gr = g + row * 256;
    #pragma unroll
    for (int h = 0; h < HH; h++) {
        float v = gr[h * 32 + lane];
        float s = v * as;
        float d = v * ad;
        #pragma unroll
        for (int off = 16; off; off >>= 1) {
            s += __shfl_down_sync(0xFFFFFFFFu, s, off);
            d += __shfl_down_sync(0xFFFFFFFFu, d, off);
        }
        if (lane == 0) {
            src[row * HH + h] = s;
            dst[row * HH + h] = d;
        }
    }
}

// ---------------- denom[b,j,h] = sum_i adj[i,j]*exp(lrelu(src_i+dst_j)) ----------------
// grid (NN/32, BB), block (32,8): x = j within tile, y = i-strip
__global__ __launch_bounds__(256) void denom_k(const int* __restrict__ adj,
                                               const float* __restrict__ src,
                                               const float* __restrict__ dst,
                                               float* __restrict__ den) {
    __shared__ float ss[NN][HH];      // src for whole batch row set: 32KB
    __shared__ float red[32][HH];
    const int b  = blockIdx.y;
    const int j0 = blockIdx.x * 32;
    const int tid = threadIdx.y * 32 + threadIdx.x;
    const float* sb = src + b * NN * HH;
    for (int i = tid; i < NN * HH; i += 256) ((float*)ss)[i] = sb[i];
    const int jt = threadIdx.x;
    const int it = threadIdx.y;
    float dr[HH];
    #pragma unroll
    for (int h = 0; h < HH; h++) dr[h] = dst[b * NN * HH + (j0 + jt) * HH + h];
    float acc[HH] = {};
    if (it == 0) {
        #pragma unroll
        for (int h = 0; h < HH; h++) red[jt][h] = 0.f;
    }
    __syncthreads();
    for (int i = it; i < NN; i += 8) {
        const float av = (float)adj[i * NN + j0 + jt];
        #pragma unroll
        for (int h = 0; h < HH; h++) {
            float e = ss[i][h] + dr[h];
            e = e >= 0.f ? e : LALPHA * e;
            acc[h] = fmaf(av, __expf(e), acc[h]);
        }
    }
    #pragma unroll
    for (int h = 0; h < HH; h++) atomicAdd(&red[jt][h], acc[h]);
    __syncthreads();
    if (it == 0) {
        #pragma unroll
        for (int h = 0; h < HH; h++)
            den[b * NN * HH + (j0 + jt) * HH + h] = red[jt][h];
    }
}

// ---------------- gs = g / denom ----------------
__global__ __launch_bounds__(256) void scaleg_k(const float* __restrict__ g,
                                                const float* __restrict__ den,
                                                float* __restrict__ gs) {
    const int idx = blockIdx.x * 256 + threadIdx.x;    // < BB*NN*FF
    const int col = idx & 255;
    const int h   = col >> 5;
    const int row = idx >> 8;                          // b*NN + j
    gs[idx] = g[idx] / den[row * HH + h];
}

// ---------------- attention contraction ----------------
// out[b,i,c] = sum_j adj[i,j]*exp(lrelu(src[i,h]+dst[j,h])) * gs[j,c],  h=c>>5
// grid (NN/16, BB), 256 threads. Stage w-tile [8 heads][16 i][64 j] in smem:
// writes lane-coalesced over j, reads warp-uniform float4 broadcast.
__global__ __launch_bounds__(256) void attn_k(const int* __restrict__ adj,
                                              const float* __restrict__ src,
                                              const float* __restrict__ dst,
                                              const float* __restrict__ gs,
                                              float* __restrict__ out) {
    __shared__ __align__(16) float ws[HH][16][64];   // 32KB
    __shared__ float ss[16][HH];
    const int b  = blockIdx.y;
    const int i0 = blockIdx.x * 16;
    const int tid = threadIdx.x;
    const int c  = tid;           // output column 0..255
    const int hr = tid >> 5;      // head for read phase
    const int jl = tid & 63;      // j-lane for write phase
    const int ig = tid >> 6;      // i-group 0..3
    if (tid < 128) ss[tid >> 3][tid & 7] = src[b * NN * HH + (i0 + (tid >> 3)) * HH + (tid & 7)];
    float acc[16] = {};
    const float* dstb = dst + b * NN * HH;
    const float* gsb  = gs  + b * NN * FF;
    for (int jc = 0; jc < NN; jc += 64) {
        float dr[HH];
        #pragma unroll
        for (int h = 0; h < HH; h++) dr[h] = dstb[(jc + jl) * HH + h];
        __syncthreads();   // ws consumed (prev iter) / ss ready (first iter)
        #pragma unroll
        for (int k = 0; k < 4; k++) {
            const int il = ig * 4 + k;
            const float av = (float)adj[(i0 + il) * NN + jc + jl];
            #pragma unroll
            for (int h = 0; h < HH; h++) {
                float e = ss[il][h] + dr[h];
                e = e >= 0.f ? e : LALPHA * e;
                ws[h][il][jl] = av * __expf(e);
            }
        }
        __syncthreads();
        const float* gcol = gsb + jc * FF + c;
        #pragma unroll
        for (int jq = 0; jq < 16; jq++) {
            const float g0 = gcol[(4 * jq + 0) * FF];
            const float g1 = gcol[(4 * jq + 1) * FF];
            const float g2 = gcol[(4 * jq + 2) * FF];
            const float g3 = gcol[(4 * jq + 3) * FF];
            #pragma unroll
            for (int il = 0; il < 16; il++) {
                const float4 w = *(const float4*)&ws[hr][il][4 * jq];
                acc[il] = fmaf(w.x, g0, acc[il]);
                acc[il] = fmaf(w.y, g1, acc[il]);
                acc[il] = fmaf(w.z, g2, acc[il]);
                acc[il] = fmaf(w.w, g3, acc[il]);
            }
        }
    }
    #pragma unroll
    for (int il = 0; il < 16; il++)
        out[b * NN * FF + (i0 + il) * FF + c] = acc[il];
}

// ---------------- BatchNorm over batch dim (B=4) + ReLU (+ residual) ----------------
template <bool ADDRES>
__global__ __launch_bounds__(256) void bn_k(const float* __restrict__ y,
                                            const float* __restrict__ gamma,
                                            const float* __restrict__ beta,
                                            const float* __restrict__ resid,
                                            float* __restrict__ out) {
    const int p = blockIdx.x * 256 + threadIdx.x;   // feature index < NF
    const float v0 = y[p];
    const float v1 = y[NF + p];
    const float v2 = y[2 * NF + p];
    const float v3 = y[3 * NF + p];
    const float mu = 0.25f * (v0 + v1 + v2 + v3);
    const float d0 = v0 - mu, d1 = v1 - mu, d2 = v2 - mu, d3 = v3 - mu;
    const float var = 0.25f * (d0 * d0 + d1 * d1 + d2 * d2 + d3 * d3);
    const float rs = rsqrtf(var + 1e-5f);
    const float ga = gamma[p] * rs;
    const float be = beta[p];
    float o0 = fmaxf(fmaf(ga, d0, be), 0.f);
    float o1 = fmaxf(fmaf(ga, d1, be), 0.f);
    float o2 = fmaxf(fmaf(ga, d2, be), 0.f);
    float o3 = fmaxf(fmaf(ga, d3, be), 0.f);
    if (ADDRES) {
        o0 += resid[p];
        o1 += resid[NF + p];
        o2 += resid[2 * NF + p];
        o3 += resid[3 * NF + p];
    }
    out[p] = o0;
    out[NF + p] = o1;
    out[2 * NF + p] = o2;
    out[3 * NF + p] = o3;
}

// ---------------- launch ----------------
extern "C" void kernel_launch(void* const* d_in, const int* in_sizes, int n_in,
                              void* d_out, int out_size) {
    const float* x  = (const float*)d_in[0];
    const int*  adj = (const int*)  d_in[1];
    const float* W1 = (const float*)d_in[2];
    const float* a1 = (const float*)d_in[3];
    const float* g1 = (const float*)d_in[4];
    const float* b1 = (const float*)d_in[5];
    const float* W2 = (const float*)d_in[6];
    const float* a2 = (const float*)d_in[7];
    const float* g2 = (const float*)d_in[8];
    const float* b2 = (const float*)d_in[9];
    float* out = (float*)d_out;

    static float *pg = nullptr, *pgs, *patt, *py, *psrc, *pdst, *pden;
    if (!pg) {
        cudaGetSymbolAddress((void**)&pg,   g_buf);
        cudaGetSymbolAddress((void**)&pgs,  gs_buf);
        cudaGetSymbolAddress((void**)&patt, att_buf);
        cudaGetSymbolAddress((void**)&py,   y_buf);
        cudaGetSymbolAddress((void**)&psrc, src_buf);
        cudaGetSymbolAddress((void**)&pdst, dst_buf);
        cudaGetSymbolAddress((void**)&pden, den_buf);
    }

    // ---- layer 1 ----
    gemm_nt<<<dim3(4, 64), 256>>>(x, W1, pg);
    srcdst_k<<<512, dim3(32, 8)>>>(pg, a1, psrc, pdst);
    denom_k<<<dim3(32, 4), dim3(32, 8)>>>(adj, psrc, pdst, pden);
    scaleg_k<<<4096, 256>>>(pg, pden, pgs);
    attn_k<<<dim3(64, 4), 256>>>(adj, psrc, pdst, pgs, patt);
    bn_k<false><<<1024, 256>>>(patt, g1, b1, nullptr, py);

    // ---- layer 2 ----
    gemm_nt<<<dim3(4, 64), 256>>>(py, W2, pg);
    srcdst_k<<<512, dim3(32, 8)>>>(pg, a2, psrc, pdst);
    denom_k<<<dim3(32, 4), dim3(32, 8)>>>(adj, psrc, pdst, pden);
    scaleg_k<<<4096, 256>>>(pg, pden, pgs);
    attn_k<<<dim3(64, 4), 256>>>(adj, psrc, pdst, pgs, patt);
    bn_k<true><<<1024, 256>>>(patt, g2, b2, x, out);
}

// round 2
// speedup vs baseline: 1.1637x; 1.1637x over previous
#include <cuda_runtime.h>

#define BB 4
#define NN 1024
#define FF 256
#define HH 8
#define NF (NN*FF)

// ---------------- scratch (no allocations allowed) ----------------
__device__ float g_buf  [BB*NN*FF];
__device__ float att_buf[BB*NN*FF];
__device__ float y_buf  [BB*NN*FF];
__device__ float src_buf[BB*NN*HH];
__device__ float dst_buf[BB*NN*HH];
__device__ float den_buf[BB*NN*HH];

// ---------------- f32x2 helpers (sm_100+) ----------------
__device__ __forceinline__ unsigned long long pack2(float a, float b) {
    unsigned long long r;
    asm("mov.b64 %0, {%1, %2};" : "=l"(r) : "f"(a), "f"(b));
    return r;
}
__device__ __forceinline__ void ffma2(unsigned long long& acc,
                                      unsigned long long a, unsigned long long b) {
    asm("fma.rn.f32x2 %0, %1, %2, %0;" : "+l"(acc) : "l"(a), "l"(b));
}

// ---------------- GEMM: C[m][o] = sum_k A[m][k]*W[o][k] ----------------
__global__ __launch_bounds__(256) void gemm_nt(const float* __restrict__ A,
                                               const float* __restrict__ W,
                                               float* __restrict__ C) {
    __shared__ float As[16][65];
    __shared__ float Bs[16][65];
    const int m0 = blockIdx.y * 64;
    const int o0 = blockIdx.x * 64;
    const int tx = threadIdx.x & 15;
    const int ty = threadIdx.x >> 4;
    float acc[4][4] = {};
    for (int k0 = 0; k0 < 256; k0 += 16) {
        const int c = threadIdx.x & 15;
        const int r = threadIdx.x >> 4;
        #pragma unroll
        for (int rr = 0; rr < 64; rr += 16) {
            As[c][r + rr] = A[(m0 + r + rr) * 256 + k0 + c];
            Bs[c][r + rr] = W[(o0 + r + rr) * 256 + k0 + c];
        }
        __syncthreads();
        #pragma unroll
        for (int kk = 0; kk < 16; kk++) {
            float ar[4], br[4];
            #pragma unroll
            for (int i = 0; i < 4; i++) ar[i] = As[kk][ty * 4 + i];
            #pragma unroll
            for (int i = 0; i < 4; i++) br[i] = Bs[kk][tx * 4 + i];
            #pragma unroll
            for (int a = 0; a < 4; a++)
                #pragma unroll
                for (int b = 0; b < 4; b++)
                    acc[a][b] = fmaf(ar[a], br[b], acc[a][b]);
        }
        __syncthreads();
    }
    #pragma unroll
    for (int a = 0; a < 4; a++)
        #pragma unroll
        for (int b = 0; b < 4; b++)
            C[(m0 + ty * 4 + a) * 256 + o0 + tx * 4 + b] = acc[a][b];
}

// ---------------- src/dst projections (+ zero den for this layer) ----------------
__global__ __launch_bounds__(256) void srcdst_k(const float* __restrict__ g,
                                                const float* __restrict__ a,
                                                float* __restrict__ src,
                                                float* __restrict__ dst,
                                                float* __restrict__ den) {
    const int gtid = blockIdx.x * 256 + threadIdx.y * 32 + threadIdx.x;
    if (gtid < BB * NN * HH) den[gtid] = 0.f;
    const int row  = blockIdx.x * 8 + threadIdx.y;   // 0..4095
    const int lane = threadIdx.x;
    const float as = a[lane];
    const float ad = a[32 + lane];
    const float* gr = g + row * 256;
    #pragma unroll
    for (int h = 0; h < HH; h++) {
        float v = gr[h * 32 + lane];
        float s = v * as;
        float d = v * ad;
        #pragma unroll
        for (int off = 16; off; off >>= 1) {
            s += __shfl_down_sync(0xFFFFFFFFu, s, off);
            d += __shfl_down_sync(0xFFFFFFFFu, d, off);
        }
        if (lane == 0) {
            src[row * HH + h] = s;
            dst[row * HH + h] = d;
        }
    }
}

// ---------------- denom[b,j,h] += sum_{i in chunk} adj[i,j]*exp(lrelu(src_i+dst_j)) ----------------
// grid (NN/32, BB, 4 i-chunks), block (32,8)
__global__ __launch_bounds__(256) void denom_k(const int* __restrict__ adj,
                                               const float* __restrict__ src,
                                               const float* __restrict__ dst,
                                               float* __restrict__ den) {
    __shared__ float ss[256][HH];     // 8KB: src chunk
    __shared__ float red[32][HH];
    const int b  = blockIdx.y;
    const int j0 = blockIdx.x * 32;
    const int ic = blockIdx.z * 256;
    const int tid = threadIdx.y * 32 + threadIdx.x;
    const float* sb = src + b * NN * HH + ic * HH;
    for (int i = tid; i < 256 * HH; i += 256) ((float*)ss)[i] = sb[i];
    const int jt = threadIdx.x;
    const int it = threadIdx.y;
    const float4* dp = (const float4*)(dst + b * NN * HH + (j0 + jt) * HH);
    float4 t0 = dp[0], t1 = dp[1];
    float dr[HH] = {t0.x, t0.y, t0.z, t0.w, t1.x, t1.y, t1.z, t1.w};
    if (it == 0) {
        #pragma unroll
        for (int h = 0; h < HH; h++) red[jt][h] = 0.f;
    }
    __syncthreads();
    float acc[HH] = {};
    for (int i = it; i < 256; i += 8) {
        const float av = (float)adj[(ic + i) * NN + j0 + jt];
        #pragma unroll
        for (int h = 0; h < HH; h++) {
            float e = ss[i][h] + dr[h];
            e = fmaxf(e, 0.2f * e);
            acc[h] = fmaf(av, __expf(e), acc[h]);
        }
    }
    #pragma unroll
    for (int h = 0; h < HH; h++) atomicAdd(&red[jt][h], acc[h]);
    __syncthreads();
    if (it == 0) {
        #pragma unroll
        for (int h = 0; h < HH; h++)
            atomicAdd(&den[b * NN * HH + (j0 + jt) * HH + h], red[jt][h]);
    }
}

// ---------------- den -> 1/den (in place) ----------------
__global__ __launch_bounds__(256) void rden_k(float* __restrict__ den) {
    const int i = blockIdx.x * 256 + threadIdx.x;
    den[i] = 1.0f / den[i];
}

// ---------------- attention contraction ----------------
// out[b,i,c] = sum_j adj[i,j]*exp(lrelu(src[i,h]+dst[j,h]))*rden[j,h] * g[j,c], h=c>>5
// grid (NN/8, BB), 256 threads; w-tile [8h][8i][64j] in smem; f32x2 packed FMA over j-pairs.
__global__ __launch_bounds__(256) void attn_k(const int* __restrict__ adj,
                                              const float* __restrict__ src,
                                              const float* __restrict__ dst,
                                              const float* __restrict__ rden,
                                              const float* __restrict__ g,
                                              float* __restrict__ out) {
    __shared__ __align__(16) float ws[HH][8][64];   // 16KB
    __shared__ float ss[8][HH];
    const int b  = blockIdx.y;
    const int i0 = blockIdx.x * 8;
    const int tid = threadIdx.x;
    const int c  = tid;           // output column 0..255
    const int hr = tid >> 5;      // head for read phase
    const int jl = tid & 63;      // j-lane for write phase
    const int ig = tid >> 6;      // i-group 0..3 (2 il each)
    if (tid < 64) ss[tid >> 3][tid & 7] = src[b * NN * HH + (i0 + (tid >> 3)) * HH + (tid & 7)];
    unsigned long long acc2[8];
    #pragma unroll
    for (int il = 0; il < 8; il++) acc2[il] = 0ull;
    const float* dstb = dst + b * NN * HH;
    const float* rdb  = rden + b * NN * HH;
    const float* gb   = g + b * NN * FF;
    for (int jc = 0; jc < NN; jc += 64) {
        const float4* dp = (const float4*)(dstb + (jc + jl) * HH);
        float4 t0 = dp[0], t1 = dp[1];
        float dr[HH] = {t0.x, t0.y, t0.z, t0.w, t1.x, t1.y, t1.z, t1.w};
        const float4* rp = (const float4*)(rdb + (jc + jl) * HH);
        float4 u0 = rp[0], u1 = rp[1];
        float rr[HH] = {u0.x, u0.y, u0.z, u0.w, u1.x, u1.y, u1.z, u1.w};
        __syncthreads();   // ws consumed (prev iter) / ss ready (first iter)
        #pragma unroll
        for (int k = 0; k < 2; k++) {
            const int il = ig * 2 + k;
            const float av = (float)adj[(i0 + il) * NN + jc + jl];
            #pragma unroll
            for (int h = 0; h < HH; h++) {
                float e = ss[il][h] + dr[h];
                e = fmaxf(e, 0.2f * e);
                ws[h][il][jl] = av * (__expf(e) * rr[h]);
            }
        }
        __syncthreads();
        const float* gcol = gb + jc * FF + c;
        #pragma unroll
        for (int jq = 0; jq < 16; jq++) {
            const float g0 = gcol[(4 * jq + 0) * FF];
            const float g1 = gcol[(4 * jq + 1) * FF];
            const float g2 = gcol[(4 * jq + 2) * FF];
            const float g3 = gcol[(4 * jq + 3) * FF];
            const unsigned long long gp01 = pack2(g0, g1);
            const unsigned long long gp23 = pack2(g2, g3);
            #pragma unroll
            for (int il = 0; il < 8; il++) {
                const ulonglong2 wv = *(const ulonglong2*)&ws[hr][il][4 * jq];
                ffma2(acc2[il], wv.x, gp01);
                ffma2(acc2[il], wv.y, gp23);
            }
        }
    }
    #pragma unroll
    for (int il = 0; il < 8; il++) {
        union { unsigned long long u; float2 f; } cv;
        cv.u = acc2[il];
        out[b * NN * FF + (i0 + il) * FF + c] = cv.f.x + cv.f.y;
    }
}

// ---------------- BatchNorm over batch dim (B=4) + ReLU (+ residual) ----------------
template <bool ADDRES>
__global__ __launch_bounds__(256) void bn_k(const float* __restrict__ y,
                                            const float* __restrict__ gamma,
                                            const float* __restrict__ beta,
                                            const float* __restrict__ resid,
                                            float* __restrict__ out) {
    const int p = blockIdx.x * 256 + threadIdx.x;   // feature index < NF
    const float v0 = y[p];
    const float v1 = y[NF + p];
    const float v2 = y[2 * NF + p];
    const float v3 = y[3 * NF + p];
    const float mu = 0.25f * (v0 + v1 + v2 + v3);
    const float d0 = v0 - mu, d1 = v1 - mu, d2 = v2 - mu, d3 = v3 - mu;
    const float var = 0.25f * (d0 * d0 + d1 * d1 + d2 * d2 + d3 * d3);
    const float rs = rsqrtf(var + 1e-5f);
    const float ga = gamma[p] * rs;
    const float be = beta[p];
    float o0 = fmaxf(fmaf(ga, d0, be), 0.f);
    float o1 = fmaxf(fmaf(ga, d1, be), 0.f);
    float o2 = fmaxf(fmaf(ga, d2, be), 0.f);
    float o3 = fmaxf(fmaf(ga, d3, be), 0.f);
    if (ADDRES) {
        o0 += resid[p];
        o1 += resid[NF + p];
        o2 += resid[2 * NF + p];
        o3 += resid[3 * NF + p];
    }
    out[p] = o0;
    out[NF + p] = o1;
    out[2 * NF + p] = o2;
    out[3 * NF + p] = o3;
}

// ---------------- launch ----------------
extern "C" void kernel_launch(void* const* d_in, const int* in_sizes, int n_in,
                              void* d_out, int out_size) {
    const float* x  = (const float*)d_in[0];
    const int*  adj = (const int*)  d_in[1];
    const float* W1 = (const float*)d_in[2];
    const float* a1 = (const float*)d_in[3];
    const float* g1 = (const float*)d_in[4];
    const float* b1 = (const float*)d_in[5];
    const float* W2 = (const float*)d_in[6];
    const float* a2 = (const float*)d_in[7];
    const float* g2 = (const float*)d_in[8];
    const float* b2 = (const float*)d_in[9];
    float* out = (float*)d_out;

    static float *pg = nullptr, *patt, *py, *psrc, *pdst, *pden;
    if (!pg) {
        cudaGetSymbolAddress((void**)&pg,   g_buf);
        cudaGetSymbolAddress((void**)&patt, att_buf);
        cudaGetSymbolAddress((void**)&py,   y_buf);
        cudaGetSymbolAddress((void**)&psrc, src_buf);
        cudaGetSymbolAddress((void**)&pdst, dst_buf);
        cudaGetSymbolAddress((void**)&pden, den_buf);
    }

    // ---- layer 1 ----
    gemm_nt<<<dim3(4, 64), 256>>>(x, W1, pg);
    srcdst_k<<<512, dim3(32, 8)>>>(pg, a1, psrc, pdst, pden);
    denom_k<<<dim3(32, 4, 4), dim3(32, 8)>>>(adj, psrc, pdst, pden);
    rden_k<<<128, 256>>>(pden);
    attn_k<<<dim3(128, 4), 256>>>(adj, psrc, pdst, pden, pg, patt);
    bn_k<false><<<1024, 256>>>(patt, g1, b1, nullptr, py);

    // ---- layer 2 ----
    gemm_nt<<<dim3(4, 64), 256>>>(py, W2, pg);
    srcdst_k<<<512, dim3(32, 8)>>>(pg, a2, psrc, pdst, pden);
    denom_k<<<dim3(32, 4, 4), dim3(32, 8)>>>(adj, psrc, pdst, pden);
    rden_k<<<128, 256>>>(pden);
    attn_k<<<dim3(128, 4), 256>>>(adj, psrc, pdst, pden, pg, patt);
    bn_k<true><<<1024, 256>>>(patt, g2, b2, x, out);
}

// round 3
// speedup vs baseline: 1.1640x; 1.0003x over previous
#include <cuda_runtime.h>

#define BB 4
#define NN 1024
#define FF 256
#define HH 8
#define NF (NN*FF)

// ---------------- scratch (no allocations allowed) ----------------
__device__ float g_buf  [BB*NN*FF];
__device__ float att_buf[BB*NN*FF];
__device__ float y_buf  [BB*NN*FF];
__device__ float src_buf[BB*NN*HH];
__device__ float dst_buf[BB*NN*HH];
__device__ float den_buf[BB*NN*HH];

// ---------------- f32x2 helpers (sm_100+) ----------------
__device__ __forceinline__ unsigned long long pack2(float a, float b) {
    unsigned long long r;
    asm("mov.b64 %0, {%1, %2};" : "=l"(r) : "f"(a), "f"(b));
    return r;
}
__device__ __forceinline__ void ffma2(unsigned long long& acc,
                                      unsigned long long a, unsigned long long b) {
    asm("fma.rn.f32x2 %0, %1, %2, %0;" : "+l"(acc) : "l"(a), "l"(b));
}
union F4U2 { float4 f; ulonglong2 u; };

// ---------------- GEMM: C[m][o] = sum_k A[m][k]*W[o][k] ----------------
// M=4096, K=256, O=256. Tile 64x64x16, 256 threads, 4x4 micro via f32x2.
__global__ __launch_bounds__(256) void gemm_nt(const float* __restrict__ A,
                                               const float* __restrict__ W,
                                               float* __restrict__ C) {
    __shared__ float As[16][68];
    __shared__ float Bs[16][68];
    const int m0 = blockIdx.y * 64;
    const int o0 = blockIdx.x * 64;
    const int tx = threadIdx.x & 15;
    const int ty = threadIdx.x >> 4;
    unsigned long long acc2[4][2];
    #pragma unroll
    for (int a = 0; a < 4; a++) { acc2[a][0] = 0ull; acc2[a][1] = 0ull; }
    for (int k0 = 0; k0 < 256; k0 += 16) {
        const int c = threadIdx.x & 15;
        const int r = threadIdx.x >> 4;
        #pragma unroll
        for (int rr = 0; rr < 64; rr += 16) {
            As[c][r + rr] = A[(m0 + r + rr) * 256 + k0 + c];
            Bs[c][r + rr] = W[(o0 + r + rr) * 256 + k0 + c];
        }
        __syncthreads();
        #pragma unroll
        for (int kk = 0; kk < 16; kk++) {
            F4U2 a4, b4;
            a4.f = *(const float4*)&As[kk][ty * 4];
            b4.f = *(const float4*)&Bs[kk][tx * 4];
            const unsigned long long ap0 = pack2(a4.f.x, a4.f.x);
            const unsigned long long ap1 = pack2(a4.f.y, a4.f.y);
            const unsigned long long ap2 = pack2(a4.f.z, a4.f.z);
            const unsigned long long ap3 = pack2(a4.f.w, a4.f.w);
            ffma2(acc2[0][0], ap0, b4.u.x); ffma2(acc2[0][1], ap0, b4.u.y);
            ffma2(acc2[1][0], ap1, b4.u.x); ffma2(acc2[1][1], ap1, b4.u.y);
            ffma2(acc2[2][0], ap2, b4.u.x); ffma2(acc2[2][1], ap2, b4.u.y);
            ffma2(acc2[3][0], ap3, b4.u.x); ffma2(acc2[3][1], ap3, b4.u.y);
        }
        __syncthreads();
    }
    #pragma unroll
    for (int a = 0; a < 4; a++) {
        F4U2 o;
        o.u.x = acc2[a][0];
        o.u.y = acc2[a][1];
        *(float4*)&C[(m0 + ty * 4 + a) * 256 + o0 + tx * 4] = o.f;
    }
}

// ---------------- src/dst projections ----------------
__global__ __launch_bounds__(256) void srcdst_k(const float* __restrict__ g,
                                                const float* __restrict__ a,
                                                float* __restrict__ src,
                                                float* __restrict__ dst) {
    const int row  = blockIdx.x * 8 + threadIdx.y;   // 0..4095
    const int lane = threadIdx.x;
    const float as = a[lane];
    const float ad = a[32 + lane];
    const float* gr = g + row * 256;
    #pragma unroll
    for (int h = 0; h < HH; h++) {
        float v = gr[h * 32 + lane];
        float s = v * as;
        float d = v * ad;
        #pragma unroll
        for (int off = 16; off; off >>= 1) {
            s += __shfl_down_sync(0xFFFFFFFFu, s, off);
            d += __shfl_down_sync(0xFFFFFFFFu, d, off);
        }
        if (lane == 0) {
            src[row * HH + h] = s;
            dst[row * HH + h] = d;
        }
    }
}

// ---------------- rden[b,j,h] = 1 / sum_i adj[i,j]*exp(lrelu(src_i+dst_j)) ----------------
// single pass over i: grid (NN/32, BB), block (32,16)
__global__ __launch_bounds__(512) void denom_k(const int* __restrict__ adj,
                                               const float* __restrict__ src,
                                               const float* __restrict__ dst,
                                               float* __restrict__ rden) {
    __shared__ float ss[NN][HH];      // 32KB: src for whole batch
    __shared__ float red[32][HH];
    const int b  = blockIdx.y;
    const int j0 = blockIdx.x * 32;
    const int tid = threadIdx.y * 32 + threadIdx.x;
    const float4* sb = (const float4*)(src + b * NN * HH);
    float4* ssv = (float4*)ss;
    for (int i = tid; i < NN * HH / 4; i += 512) ssv[i] = sb[i];
    const int jt = threadIdx.x;
    const int it = threadIdx.y;
    const float4* dp = (const float4*)(dst + b * NN * HH + (j0 + jt) * HH);
    float4 t0 = dp[0], t1 = dp[1];
    float dr[HH] = {t0.x, t0.y, t0.z, t0.w, t1.x, t1.y, t1.z, t1.w};
    if (it == 0) {
        #pragma unroll
        for (int h = 0; h < HH; h++) red[jt][h] = 0.f;
    }
    __syncthreads();
    float acc[HH] = {};
    for (int i = it; i < NN; i += 16) {
        const float av = (float)adj[i * NN + j0 + jt];
        #pragma unroll
        for (int h = 0; h < HH; h++) {
            float e = ss[i][h] + dr[h];
            e = fmaxf(e, 0.2f * e);
            acc[h] = fmaf(av, __expf(e), acc[h]);
        }
    }
    #pragma unroll
    for (int h = 0; h < HH; h++) atomicAdd(&red[jt][h], acc[h]);
    __syncthreads();
    if (it == 0) {
        #pragma unroll
        for (int h = 0; h < HH; h++)
            rden[b * NN * HH + (j0 + jt) * HH + h] = 1.0f / red[jt][h];
    }
}

// ---------------- attention contraction ----------------
// out[b,i,c] = sum_j adj[i,j]*exp(lrelu(src[i,h]+dst[j,h]))*rden[j,h] * g[j,c]
// grid (NN/16, 2 head-halves, BB), 128 threads. w-tile [4h][16i][64j] smem.
__global__ __launch_bounds__(128) void attn_k(const int* __restrict__ adj,
                                              const float* __restrict__ src,
                                              const float* __restrict__ dst,
                                              const float* __restrict__ rden,
                                              const float* __restrict__ g,
                                              float* __restrict__ out) {
    __shared__ __align__(16) float ws[4][16][64];   // 16KB
    __shared__ float ss[16][HH];
    const int b  = blockIdx.z;
    const int hb = blockIdx.y * 4;            // head base for this block (0 or 4)
    const int i0 = blockIdx.x * 16;
    const int tid = threadIdx.x;              // 0..127
    const int hr = tid >> 5;                  // local head 0..3 for read phase
    const int jl = tid & 63;                  // j-lane for write phase
    const int ig = tid >> 6;                  // i-group 0..1 (8 il each)
    // full src rows for this i-tile (all 8 heads; only hb..hb+3 used)
    ss[tid >> 3][tid & 7] = src[b * NN * HH + (i0 + (tid >> 3)) * HH + (tid & 7)];
    unsigned long long acc2[16];
    #pragma unroll
    for (int il = 0; il < 16; il++) acc2[il] = 0ull;
    const float* dstb = dst + b * NN * HH + hb;
    const float* rdb  = rden + b * NN * HH + hb;
    const float* gb   = g + b * NN * FF + hb * 32;
    for (int jc = 0; jc < NN; jc += 64) {
        const float4 t = *(const float4*)(dstb + (jc + jl) * HH);
        const float4 u = *(const float4*)(rdb + (jc + jl) * HH);
        const float dr[4] = {t.x, t.y, t.z, t.w};
        const float rr[4] = {u.x, u.y, u.z, u.w};
        __syncthreads();   // ws consumed (prev iter) / ss ready (first iter)
        #pragma unroll
        for (int k = 0; k < 8; k++) {
            const int il = ig * 8 + k;
            const float av = (float)adj[(i0 + il) * NN + jc + jl];
            #pragma unroll
            for (int h = 0; h < 4; h++) {
                float e = ss[il][hb + h] + dr[h];
                e = fmaxf(e, 0.2f * e);
                ws[h][il][jl] = av * (__expf(e) * rr[h]);
            }
        }
        __syncthreads();
        const float* gcol = gb + jc * FF + tid;
        #pragma unroll
        for (int jq = 0; jq < 16; jq++) {
            const float g0 = gcol[(4 * jq + 0) * FF];
            const float g1 = gcol[(4 * jq + 1) * FF];
            const float g2 = gcol[(4 * jq + 2) * FF];
            const float g3 = gcol[(4 * jq + 3) * FF];
            const unsigned long long gp01 = pack2(g0, g1);
            const unsigned long long gp23 = pack2(g2, g3);
            #pragma unroll
            for (int il = 0; il < 16; il++) {
                const ulonglong2 wv = *(const ulonglong2*)&ws[hr][il][4 * jq];
                ffma2(acc2[il], wv.x, gp01);
                ffma2(acc2[il], wv.y, gp23);
            }
        }
    }
    #pragma unroll
    for (int il = 0; il < 16; il++) {
        union { unsigned long long u; float2 f; } cv;
        cv.u = acc2[il];
        out[b * NN * FF + (i0 + il) * FF + hb * 32 + tid] = cv.f.x + cv.f.y;
    }
}

// ---------------- BatchNorm over batch dim (B=4) + ReLU (+ residual) ----------------
template <bool ADDRES>
__global__ __launch_bounds__(256) void bn_k(const float* __restrict__ y,
                                            const float* __restrict__ gamma,
                                            const float* __restrict__ beta,
                                            const float* __restrict__ resid,
                                            float* __restrict__ out) {
    const int p = blockIdx.x * 256 + threadIdx.x;   // feature index < NF
    const float v0 = y[p];
    const float v1 = y[NF + p];
    const float v2 = y[2 * NF + p];
    const float v3 = y[3 * NF + p];
    const float mu = 0.25f * (v0 + v1 + v2 + v3);
    const float d0 = v0 - mu, d1 = v1 - mu, d2 = v2 - mu, d3 = v3 - mu;
    const float var = 0.25f * (d0 * d0 + d1 * d1 + d2 * d2 + d3 * d3);
    const float rs = rsqrtf(var + 1e-5f);
    const float ga = gamma[p] * rs;
    const float be = beta[p];
    float o0 = fmaxf(fmaf(ga, d0, be), 0.f);
    float o1 = fmaxf(fmaf(ga, d1, be), 0.f);
    float o2 = fmaxf(fmaf(ga, d2, be), 0.f);
    float o3 = fmaxf(fmaf(ga, d3, be), 0.f);
    if (ADDRES) {
        o0 += resid[p];
        o1 += resid[NF + p];
        o2 += resid[2 * NF + p];
        o3 += resid[3 * NF + p];
    }
    out[p] = o0;
    out[NF + p] = o1;
    out[2 * NF + p] = o2;
    out[3 * NF + p] = o3;
}

// ---------------- launch ----------------
extern "C" void kernel_launch(void* const* d_in, const int* in_sizes, int n_in,
                              void* d_out, int out_size) {
    const float* x  = (const float*)d_in[0];
    const int*  adj = (const int*)  d_in[1];
    const float* W1 = (const float*)d_in[2];
    const float* a1 = (const float*)d_in[3];
    const float* g1 = (const float*)d_in[4];
    const float* b1 = (const float*)d_in[5];
    const float* W2 = (const float*)d_in[6];
    const float* a2 = (const float*)d_in[7];
    const float* g2 = (const float*)d_in[8];
    const float* b2 = (const float*)d_in[9];
    float* out = (float*)d_out;

    static float *pg = nullptr, *patt, *py, *psrc, *pdst, *pden;
    if (!pg) {
        cudaGetSymbolAddress((void**)&pg,   g_buf);
        cudaGetSymbolAddress((void**)&patt, att_buf);
        cudaGetSymbolAddress((void**)&py,   y_buf);
        cudaGetSymbolAddress((void**)&psrc, src_buf);
        cudaGetSymbolAddress((void**)&pdst, dst_buf);
        cudaGetSymbolAddress((void**)&pden, den_buf);
    }

    // ---- layer 1 ----
    gemm_nt<<<dim3(4, 64), 256>>>(x, W1, pg);
    srcdst_k<<<512, dim3(32, 8)>>>(pg, a1, psrc, pdst);
    denom_k<<<dim3(32, 4), dim3(32, 16)>>>(adj, psrc, pdst, pden);
    attn_k<<<dim3(64, 2, 4), 128>>>(adj, psrc, pdst, pden, pg, patt);
    bn_k<false><<<1024, 256>>>(patt, g1, b1, nullptr, py);

    // ---- layer 2 ----
    gemm_nt<<<dim3(4, 64), 256>>>(py, W2, pg);
    srcdst_k<<<512, dim3(32, 8)>>>(pg, a2, psrc, pdst);
    denom_k<<<dim3(32, 4), dim3(32, 16)>>>(adj, psrc, pdst, pden);
    attn_k<<<dim3(64, 2, 4), 128>>>(adj, psrc, pdst, pden, pg, patt);
    bn_k<true><<<1024, 256>>>(patt, g2, b2, x, out);
}

// round 4
// speedup vs baseline: 1.2081x; 1.0378x over previous
#include <cuda_runtime.h>

#define BB 4
#define NN 1024
#define FF 256
#define HH 8
#define NF (NN*FF)

// ---------------- scratch (no allocations allowed) ----------------
__device__ float g_buf  [BB*NN*FF];
__device__ float p0_buf [BB*NN*FF];
__device__ float p1_buf [BB*NN*FF];
__device__ float y_buf  [BB*NN*FF];
__device__ float src_buf[BB*NN*HH];
__device__ float dst_buf[BB*NN*HH];
__device__ float den_buf[BB*NN*HH];

// ---------------- f32x2 helpers (sm_100+) ----------------
__device__ __forceinline__ unsigned long long pack2(float a, float b) {
    unsigned long long r;
    asm("mov.b64 %0, {%1, %2};" : "=l"(r) : "f"(a), "f"(b));
    return r;
}
__device__ __forceinline__ void ffma2(unsigned long long& acc,
                                      unsigned long long a, unsigned long long b) {
    asm("fma.rn.f32x2 %0, %1, %2, %0;" : "+l"(acc) : "l"(a), "l"(b));
}
union F4U2 { float4 f; ulonglong2 u; };

// ---------------- GEMM: C[m][o] = sum_k A[m][k]*W[o][k] ----------------
__global__ __launch_bounds__(256) void gemm_nt(const float* __restrict__ A,
                                               const float* __restrict__ W,
                                               float* __restrict__ C) {
    __shared__ float As[16][68];
    __shared__ float Bs[16][68];
    const int m0 = blockIdx.y * 64;
    const int o0 = blockIdx.x * 64;
    const int tx = threadIdx.x & 15;
    const int ty = threadIdx.x >> 4;
    unsigned long long acc2[4][2];
    #pragma unroll
    for (int a = 0; a < 4; a++) { acc2[a][0] = 0ull; acc2[a][1] = 0ull; }
    for (int k0 = 0; k0 < 256; k0 += 16) {
        const int c = threadIdx.x & 15;
        const int r = threadIdx.x >> 4;
        #pragma unroll
        for (int rr = 0; rr < 64; rr += 16) {
            As[c][r + rr] = A[(m0 + r + rr) * 256 + k0 + c];
            Bs[c][r + rr] = W[(o0 + r + rr) * 256 + k0 + c];
        }
        __syncthreads();
        #pragma unroll
        for (int kk = 0; kk < 16; kk++) {
            F4U2 a4, b4;
            a4.f = *(const float4*)&As[kk][ty * 4];
            b4.f = *(const float4*)&Bs[kk][tx * 4];
            const unsigned long long ap0 = pack2(a4.f.x, a4.f.x);
            const unsigned long long ap1 = pack2(a4.f.y, a4.f.y);
            const unsigned long long ap2 = pack2(a4.f.z, a4.f.z);
            const unsigned long long ap3 = pack2(a4.f.w, a4.f.w);
            ffma2(acc2[0][0], ap0, b4.u.x); ffma2(acc2[0][1], ap0, b4.u.y);
            ffma2(acc2[1][0], ap1, b4.u.x); ffma2(acc2[1][1], ap1, b4.u.y);
            ffma2(acc2[2][0], ap2, b4.u.x); ffma2(acc2[2][1], ap2, b4.u.y);
            ffma2(acc2[3][0], ap3, b4.u.x); ffma2(acc2[3][1], ap3, b4.u.y);
        }
        __syncthreads();
    }
    #pragma unroll
    for (int a = 0; a < 4; a++) {
        F4U2 o;
        o.u.x = acc2[a][0];
        o.u.y = acc2[a][1];
        *(float4*)&C[(m0 + ty * 4 + a) * 256 + o0 + tx * 4] = o.f;
    }
}

// ---------------- src/dst projections ----------------
__global__ __launch_bounds__(256) void srcdst_k(const float* __restrict__ g,
                                                const float* __restrict__ a,
                                                float* __restrict__ src,
                                                float* __restrict__ dst) {
    const int row  = blockIdx.x * 8 + threadIdx.y;   // 0..4095
    const int lane = threadIdx.x;
    const float as = a[lane];
    const float ad = a[32 + lane];
    const float* gr = g + row * 256;
    #pragma unroll
    for (int h = 0; h < HH; h++) {
        float v = gr[h * 32 + lane];
        float s = v * as;
        float d = v * ad;
        #pragma unroll
        for (int off = 16; off; off >>= 1) {
            s += __shfl_down_sync(0xFFFFFFFFu, s, off);
            d += __shfl_down_sync(0xFFFFFFFFu, d, off);
        }
        if (lane == 0) {
            src[row * HH + h] = s;
            dst[row * HH + h] = d;
        }
    }
}

// ---------------- rden[b,j,h] = 1 / sum_i adj[i,j]*exp(lrelu(src_i+dst_j)) ----------------
__global__ __launch_bounds__(512) void denom_k(const int* __restrict__ adj,
                                               const float* __restrict__ src,
                                               const float* __restrict__ dst,
                                               float* __restrict__ rden) {
    __shared__ float ss[NN][HH];      // 32KB: src for whole batch
    __shared__ float red[32][HH];
    const int b  = blockIdx.y;
    const int j0 = blockIdx.x * 32;
    const int tid = threadIdx.y * 32 + threadIdx.x;
    const float4* sb = (const float4*)(src + b * NN * HH);
    float4* ssv = (float4*)ss;
    for (int i = tid; i < NN * HH / 4; i += 512) ssv[i] = sb[i];
    const int jt = threadIdx.x;
    const int it = threadIdx.y;
    const float4* dp = (const float4*)(dst + b * NN * HH + (j0 + jt) * HH);
    float4 t0 = dp[0], t1 = dp[1];
    float dr[HH] = {t0.x, t0.y, t0.z, t0.w, t1.x, t1.y, t1.z, t1.w};
    if (it == 0) {
        #pragma unroll
        for (int h = 0; h < HH; h++) red[jt][h] = 0.f;
    }
    __syncthreads();
    float acc[HH] = {};
    for (int i = it; i < NN; i += 16) {
        const float av = (float)adj[i * NN + j0 + jt];
        #pragma unroll
        for (int h = 0; h < HH; h++) {
            float e = ss[i][h] + dr[h];
            e = fmaxf(e, 0.2f * e);
            acc[h] = fmaf(av, __expf(e), acc[h]);
        }
    }
    #pragma unroll
    for (int h = 0; h < HH; h++) atomicAdd(&red[jt][h], acc[h]);
    __syncthreads();
    if (it == 0) {
        #pragma unroll
        for (int h = 0; h < HH; h++)
            rden[b * NN * HH + (j0 + jt) * HH + h] = 1.0f / red[jt][h];
    }
}

// ---------------- attention contraction (j-split x2) ----------------
// partial[b,i,c] = sum_{j in half} adj[i,j]*exp(lrelu(src[i,h]+dst[j,h]))*rden[j,h]*g[j,c]
// grid (NN/16, 4 = 2 head-halves x 2 j-halves, BB), 128 threads.
__global__ __launch_bounds__(128) void attn_k(const int* __restrict__ adj,
                                              const float* __restrict__ src,
                                              const float* __restrict__ dst,
                                              const float* __restrict__ rden,
                                              const float* __restrict__ g,
                                              float* __restrict__ part0,
                                              float* __restrict__ part1) {
    __shared__ __align__(16) float ws[4][16][64];   // 16KB
    __shared__ float ss[16][HH];
    const int b  = blockIdx.z;
    const int hb = (blockIdx.y & 1) * 4;      // head base (0 or 4)
    const int jh = blockIdx.y >> 1;           // j-half (0 or 1)
    const int i0 = blockIdx.x * 16;
    const int tid = threadIdx.x;              // 0..127
    const int hr = tid >> 5;                  // local head 0..3 for read phase
    const int jl = tid & 63;                  // j-lane for write phase
    const int ig = tid >> 6;                  // i-group 0..1 (8 il each)
    ss[tid >> 3][tid & 7] = src[b * NN * HH + (i0 + (tid >> 3)) * HH + (tid & 7)];
    unsigned long long acc2[16];
    #pragma unroll
    for (int il = 0; il < 16; il++) acc2[il] = 0ull;
    const float* dstb = dst + b * NN * HH + hb;
    const float* rdb  = rden + b * NN * HH + hb;
    const float* gb   = g + b * NN * FF + hb * 32;
    const int j_begin = jh * (NN / 2);
    const int j_end   = j_begin + NN / 2;
    for (int jc = j_begin; jc < j_end; jc += 64) {
        const float4 t = *(const float4*)(dstb + (jc + jl) * HH);
        const float4 u = *(const float4*)(rdb + (jc + jl) * HH);
        const float dr[4] = {t.x, t.y, t.z, t.w};
        const float rr[4] = {u.x, u.y, u.z, u.w};
        __syncthreads();   // ws consumed (prev iter) / ss ready (first iter)
        #pragma unroll
        for (int k = 0; k < 8; k++) {
            const int il = ig * 8 + k;
            const float av = (float)adj[(i0 + il) * NN + jc + jl];
            #pragma unroll
            for (int h = 0; h < 4; h++) {
                float e = ss[il][hb + h] + dr[h];
                e = fmaxf(e, 0.2f * e);
                ws[h][il][jl] = av * (__expf(e) * rr[h]);
            }
        }
        __syncthreads();
        const float* gcol = gb + jc * FF + tid;
        #pragma unroll
        for (int jq = 0; jq < 16; jq++) {
            const float g0 = gcol[(4 * jq + 0) * FF];
            const float g1 = gcol[(4 * jq + 1) * FF];
            const float g2 = gcol[(4 * jq + 2) * FF];
            const float g3 = gcol[(4 * jq + 3) * FF];
            const unsigned long long gp01 = pack2(g0, g1);
            const unsigned long long gp23 = pack2(g2, g3);
            #pragma unroll
            for (int il = 0; il < 16; il++) {
                const ulonglong2 wv = *(const ulonglong2*)&ws[hr][il][4 * jq];
                ffma2(acc2[il], wv.x, gp01);
                ffma2(acc2[il], wv.y, gp23);
            }
        }
    }
    float* po = jh ? part1 : part0;
    #pragma unroll
    for (int il = 0; il < 16; il++) {
        union { unsigned long long u; float2 f; } cv;
        cv.u = acc2[il];
        po[b * NN * FF + (i0 + il) * FF + hb * 32 + tid] = cv.f.x + cv.f.y;
    }
}

// ---------------- BatchNorm over batch (B=4) + ReLU (+residual); sums 2 partials ----------------
template <bool ADDRES>
__global__ __launch_bounds__(256) void bn_k(const float* __restrict__ y0,
                                            const float* __restrict__ y1,
                                            const float* __restrict__ gamma,
                                            const float* __restrict__ beta,
                                            const float* __restrict__ resid,
                                            float* __restrict__ out) {
    const int p = blockIdx.x * 256 + threadIdx.x;   // feature index < NF
    const float v0 = y0[p]          + y1[p];
    const float v1 = y0[NF + p]     + y1[NF + p];
    const float v2 = y0[2 * NF + p] + y1[2 * NF + p];
    const float v3 = y0[3 * NF + p] + y1[3 * NF + p];
    const float mu = 0.25f * (v0 + v1 + v2 + v3);
    const float d0 = v0 - mu, d1 = v1 - mu, d2 = v2 - mu, d3 = v3 - mu;
    const float var = 0.25f * (d0 * d0 + d1 * d1 + d2 * d2 + d3 * d3);
    const float rs = rsqrtf(var + 1e-5f);
    const float ga = gamma[p] * rs;
    const float be = beta[p];
    float o0 = fmaxf(fmaf(ga, d0, be), 0.f);
    float o1 = fmaxf(fmaf(ga, d1, be), 0.f);
    float o2 = fmaxf(fmaf(ga, d2, be), 0.f);
    float o3 = fmaxf(fmaf(ga, d3, be), 0.f);
    if (ADDRES) {
        o0 += resid[p];
        o1 += resid[NF + p];
        o2 += resid[2 * NF + p];
        o3 += resid[3 * NF + p];
    }
    out[p] = o0;
    out[NF + p] = o1;
    out[2 * NF + p] = o2;
    out[3 * NF + p] = o3;
}

// ---------------- launch ----------------
extern "C" void kernel_launch(void* const* d_in, const int* in_sizes, int n_in,
                              void* d_out, int out_size) {
    const float* x  = (const float*)d_in[0];
    const int*  adj = (const int*)  d_in[1];
    const float* W1 = (const float*)d_in[2];
    const float* a1 = (const float*)d_in[3];
    const float* g1 = (const float*)d_in[4];
    const float* b1 = (const float*)d_in[5];
    const float* W2 = (const float*)d_in[6];
    const float* a2 = (const float*)d_in[7];
    const float* g2 = (const float*)d_in[8];
    const float* b2 = (const float*)d_in[9];
    float* out = (float*)d_out;

    static float *pg = nullptr, *pp0, *pp1, *py, *psrc, *pdst, *pden;
    if (!pg) {
        cudaGetSymbolAddress((void**)&pg,   g_buf);
        cudaGetSymbolAddress((void**)&pp0,  p0_buf);
        cudaGetSymbolAddress((void**)&pp1,  p1_buf);
        cudaGetSymbolAddress((void**)&py,   y_buf);
        cudaGetSymbolAddress((void**)&psrc, src_buf);
        cudaGetSymbolAddress((void**)&pdst, dst_buf);
        cudaGetSymbolAddress((void**)&pden, den_buf);
    }

    // ---- layer 1 ----
    gemm_nt<<<dim3(4, 64), 256>>>(x, W1, pg);
    srcdst_k<<<512, dim3(32, 8)>>>(pg, a1, psrc, pdst);
    denom_k<<<dim3(32, 4), dim3(32, 16)>>>(adj, psrc, pdst, pden);
    attn_k<<<dim3(64, 4, 4), 128>>>(adj, psrc, pdst, pden, pg, pp0, pp1);
    bn_k<false><<<1024, 256>>>(pp0, pp1, g1, b1, nullptr, py);

    // ---- layer 2 ----
    gemm_nt<<<dim3(4, 64), 256>>>(py, W2, pg);
    srcdst_k<<<512, dim3(32, 8)>>>(pg, a2, psrc, pdst);
    denom_k<<<dim3(32, 4), dim3(32, 16)>>>(adj, psrc, pdst, pden);
    attn_k<<<dim3(64, 4, 4), 128>>>(adj, psrc, pdst, pden, pg, pp0, pp1);
    bn_k<true><<<1024, 256>>>(pp0, pp1, g2, b2, x, out);
}

// round 7
// speedup vs baseline: 2.1809x; 1.8053x over previous
#include <cuda_runtime.h>
#include <cuda_bf16.h>
#include <cstdint>

#define BB 4
#define NN 1024
#define FF 256
#define HH 8
#define NF (NN*FF)

// ---------------- scratch (no allocations allowed) ----------------
__device__ float g_buf  [BB*NN*FF];
__device__ float att_buf[BB*NN*FF];
__device__ float y_buf  [BB*NN*FF];
__device__ float ex_buf [4*BB*HH*NN];   // es, es2, ed, ed2  each [bh][n]
__device__ float den_buf[BB*HH*NN];
__device__ unsigned adjb_buf[NN*32];    // adj bitmask: row i, 32 words over j
__device__ __nv_bfloat16 gthi_buf[BB*HH*32*NN];   // G^T hi  [bh][d][j]
__device__ __nv_bfloat16 gtlo_buf[BB*HH*32*NN];   // G^T lo

// ---------------- f32x2 helpers (sm_100+) ----------------
__device__ __forceinline__ unsigned long long pack2(float a, float b) {
    unsigned long long r;
    asm("mov.b64 %0, {%1, %2};" : "=l"(r) : "f"(a), "f"(b));
    return r;
}
__device__ __forceinline__ void ffma2(unsigned long long& acc,
                                      unsigned long long a, unsigned long long b) {
    asm("fma.rn.f32x2 %0, %1, %2, %0;" : "+l"(acc) : "l"(a), "l"(b));
}
union F4U2 { float4 f; ulonglong2 u; };

// ---------------- mma helpers ----------------
__device__ __forceinline__ uint32_t smem_u32(const void* p) {
    uint32_t a;
    asm("{ .reg .u64 t; cvta.to.shared.u64 t, %1; cvt.u32.u64 %0, t; }" : "=r"(a) : "l"(p));
    return a;
}
__device__ __forceinline__ uint32_t cvt2(float hi, float lo) {
    uint32_t r;
    asm("cvt.rn.bf16x2.f32 %0, %1, %2;" : "=r"(r) : "f"(hi), "f"(lo));
    return r;
}
__device__ __forceinline__ void ldm_x4(uint32_t& r0, uint32_t& r1, uint32_t& r2,
                                       uint32_t& r3, uint32_t addr) {
    asm volatile("ldmatrix.sync.aligned.m8n8.x4.shared.b16 {%0,%1,%2,%3}, [%4];"
                 : "=r"(r0), "=r"(r1), "=r"(r2), "=r"(r3) : "r"(addr));
}
__device__ __forceinline__ void mma16816(float* c, uint32_t a0, uint32_t a1,
                                         uint32_t a2, uint32_t a3,
                                         uint32_t b0, uint32_t b1) {
    asm volatile(
        "mma.sync.aligned.m16n8k16.row.col.f32.bf16.bf16.f32 "
        "{%0,%1,%2,%3}, {%4,%5,%6,%7}, {%8,%9}, {%0,%1,%2,%3};"
        : "+f"(c[0]), "+f"(c[1]), "+f"(c[2]), "+f"(c[3])
        : "r"(a0), "r"(a1), "r"(a2), "r"(a3), "r"(b0), "r"(b1));
}

// ---------------- GEMM: C[m][o] = sum_k A[m][k]*W[o][k] ----------------
__global__ __launch_bounds__(256) void gemm_nt(const float* __restrict__ A,
                                               const float* __restrict__ W,
                                               float* __restrict__ C) {
    __shared__ float As[16][68];
    __shared__ float Bs[16][68];
    const int m0 = blockIdx.y * 64;
    const int o0 = blockIdx.x * 64;
    const int tx = threadIdx.x & 15;
    const int ty = threadIdx.x >> 4;
    unsigned long long acc2[4][2];
    #pragma unroll
    for (int a = 0; a < 4; a++) { acc2[a][0] = 0ull; acc2[a][1] = 0ull; }
    for (int k0 = 0; k0 < 256; k0 += 16) {
        const int c = threadIdx.x & 15;
        const int r = threadIdx.x >> 4;
        #pragma unroll
        for (int rr = 0; rr < 64; rr += 16) {
            As[c][r + rr] = A[(m0 + r + rr) * 256 + k0 + c];
            Bs[c][r + rr] = W[(o0 + r + rr) * 256 + k0 + c];
        }
        __syncthreads();
        #pragma unroll
        for (int kk = 0; kk < 16; kk++) {
            F4U2 a4, b4;
            a4.f = *(const float4*)&As[kk][ty * 4];
            b4.f = *(const float4*)&Bs[kk][tx * 4];
            const unsigned long long ap0 = pack2(a4.f.x, a4.f.x);
            const unsigned long long ap1 = pack2(a4.f.y, a4.f.y);
            const unsigned long long ap2 = pack2(a4.f.z, a4.f.z);
            const unsigned long long ap3 = pack2(a4.f.w, a4.f.w);
            ffma2(acc2[0][0], ap0, b4.u.x); ffma2(acc2[0][1], ap0, b4.u.y);
            ffma2(acc2[1][0], ap1, b4.u.x); ffma2(acc2[1][1], ap1, b4.u.y);
            ffma2(acc2[2][0], ap2, b4.u.x); ffma2(acc2[2][1], ap2, b4.u.y);
            ffma2(acc2[3][0], ap3, b4.u.x); ffma2(acc2[3][1], ap3, b4.u.y);
        }
        __syncthreads();
    }
    #pragma unroll
    for (int a = 0; a < 4; a++) {
        F4U2 o;
        o.u.x = acc2[a][0];
        o.u.y = acc2[a][1];
        *(float4*)&C[(m0 + ty * 4 + a) * 256 + o0 + tx * 4] = o.f;
    }
}

// ---------------- adj -> bitmask ----------------
__global__ __launch_bounds__(32) void adjp_k(const int* __restrict__ adj,
                                             unsigned* __restrict__ adjb) {
    const int i = blockIdx.x, lane = threadIdx.x;
    #pragma unroll 4
    for (int w = 0; w < 32; ++w) {
        int v = adj[i * 1024 + w * 32 + lane];
        unsigned m = __ballot_sync(0xFFFFFFFFu, v != 0);
        if (lane == w) adjb[i * 32 + w] = m;
    }
}

// ---------------- src/dst projections -> exp tables; zero den ----------------
__global__ __launch_bounds__(256) void srcdst_k(const float* __restrict__ g,
                                                const float* __restrict__ a,
                                                float* __restrict__ es,
                                                float* __restrict__ es2,
                                                float* __restrict__ ed,
                                                float* __restrict__ ed2,
                                                float* __restrict__ den) {
    const int gtid = blockIdx.x * 256 + threadIdx.y * 32 + threadIdx.x;
    if (gtid < BB * HH * NN) den[gtid] = 0.f;
    const int row  = blockIdx.x * 8 + threadIdx.y;   // b*NN+n
    const int b = row >> 10, n = row & 1023;
    const int lane = threadIdx.x;
    const float as = a[lane];
    const float ad = a[32 + lane];
    const float* gr = g + row * 256;
    #pragma unroll
    for (int h = 0; h < HH; h++) {
        float v = gr[h * 32 + lane];
        float s = v * as;
        float d = v * ad;
        #pragma unroll
        for (int off = 16; off; off >>= 1) {
            s += __shfl_down_sync(0xFFFFFFFFu, s, off);
            d += __shfl_down_sync(0xFFFFFFFFu, d, off);
        }
        if (lane == 0) {
            const int idx = (b * HH + h) * NN + n;
            es [idx] = __expf(s);
            es2[idx] = __expf(0.2f * s);
            ed [idx] = __expf(d);
            ed2[idx] = __expf(0.2f * d);
        }
    }
}

// ---------------- den[bh][j] += sum_{i chunk} adj * w(i,j)  (no exp!) ----------------
// grid (4 i-chunks, HH, BB), 512 threads, 2 j per thread
__global__ __launch_bounds__(512) void denom_k(const unsigned* __restrict__ adjb,
                                               const float* __restrict__ es,
                                               const float* __restrict__ es2,
                                               const float* __restrict__ ed,
                                               const float* __restrict__ ed2,
                                               float* __restrict__ den) {
    __shared__ float ess[256], ess2[256];
    const int b = blockIdx.z, h = blockIdx.y, bh = b * HH + h;
    const int ic = blockIdx.x * 256;
    const int tid = threadIdx.x;
    if (tid < 256) ess[tid] = es[bh * NN + ic + tid];
    else           ess2[tid - 256] = es2[bh * NN + ic + tid - 256];
    __syncthreads();
    const int j0 = tid, j1 = tid + 512;
    const float edj0 = ed[bh * NN + j0], ed2j0 = ed2[bh * NN + j0];
    const float edj1 = ed[bh * NN + j1], ed2j1 = ed2[bh * NN + j1];
    const int w0i = j0 >> 5, w1i = j1 >> 5, s0 = j0 & 31, s1 = j1 & 31;
    float a0 = 0.f, a1 = 0.f;
    for (int i = 0; i < 256; ++i) {
        const unsigned* row = adjb + (size_t)(ic + i) * 32;
        const unsigned word0 = row[w0i];
        const unsigned word1 = row[w1i];
        const float esi = ess[i], es2i = ess2[i];
        float p = esi * edj0, p2 = es2i * ed2j0;
        float v = (p >= 1.f) ? p : p2;
        if ((word0 >> s0) & 1u) a0 += v;
        p = esi * edj1; p2 = es2i * ed2j1;
        v = (p >= 1.f) ? p : p2;
        if ((word1 >> s1) & 1u) a1 += v;
    }
    atomicAdd(&den[bh * NN + j0], a0);
    atomicAdd(&den[bh * NN + j1], a1);
}

// ---------------- gt: gs = g/den, transposed to [bh][d][j], split bf16 hi/lo ----------------
__global__ __launch_bounds__(256) void gt_k(const float* __restrict__ g,
                                            const float* __restrict__ den,
                                            __nv_bfloat16* __restrict__ gthi,
                                            __nv_bfloat16* __restrict__ gtlo) {
    __shared__ uint32_t sm[128][33];
    const int b = blockIdx.z, h = blockIdx.y, jc = blockIdx.x * 128;
    const int tid = threadIdx.x;
    const int jr0 = tid >> 3, c4 = (tid & 7) * 4;
    #pragma unroll
    for (int p = 0; p < 4; ++p) {
        const int jr = jr0 + p * 32;
        const int j = jc + jr;
        const float r = 1.0f / den[(b * HH + h) * NN + j];
        float4 v = *(const float4*)&g[(size_t)(b * NN + j) * FF + h * 32 + c4];
        float vs[4] = {v.x * r, v.y * r, v.z * r, v.w * r};
        #pragma unroll
        for (int q = 0; q < 4; ++q) {
            __nv_bfloat16 hi = __float2bfloat16(vs[q]);
            __nv_bfloat16 lo = __float2bfloat16(vs[q] - __bfloat162float(hi));
            sm[jr][c4 + q] = (uint32_t)__bfloat16_as_ushort(hi)
                           | ((uint32_t)__bfloat16_as_ushort(lo) << 16);
        }
    }
    __syncthreads();
    const int d = tid >> 3, j0 = (tid & 7) * 16;
    __align__(16) unsigned short his[16];
    __align__(16) unsigned short los[16];
    #pragma unroll
    for (int k = 0; k < 16; ++k) {
        uint32_t v = sm[j0 + k][d];
        his[k] = (unsigned short)(v & 0xFFFF);
        los[k] = (unsigned short)(v >> 16);
    }
    const size_t base = (size_t)((b * HH + h) * 32 + d) * NN + jc + j0;
    *(uint4*)&gthi[base]     = ((uint4*)his)[0];
    *(uint4*)&gthi[base + 8] = ((uint4*)his)[1];
    *(uint4*)&gtlo[base]     = ((uint4*)los)[0];
    *(uint4*)&gtlo[base + 8] = ((uint4*)los)[1];
}

// ---------------- attention via mma.sync bf16 (hi/lo 3-term) ----------------
// block = 4 warps x 16 i = 64 i rows, one (b,h). grid (16, HH, BB).
// Each warp: D[16 i x 32 d] accumulated over K=j=1024 in 16-step mma chunks.
#define GROW 272   // 128 bf16 = 256B + 16B pad (conflict-free ldmatrix)

__device__ __forceinline__ float wv(float esr, float es2r, float2 e,
                                    unsigned bits, int c) {
    const float p = esr * e.x, p2 = es2r * e.y;
    const float v = (p >= 1.0f) ? p : p2;
    return ((bits >> c) & 1u) ? v : 0.0f;
}

__global__ __launch_bounds__(128) void attn_k(const unsigned* __restrict__ adjb,
                                              const float* __restrict__ es,
                                              const float* __restrict__ es2,
                                              const float* __restrict__ ed,
                                              const float* __restrict__ ed2,
                                              const __nv_bfloat16* __restrict__ gthi,
                                              const __nv_bfloat16* __restrict__ gtlo,
                                              float* __restrict__ out) {
    __shared__ __align__(16) char GsHi[32 * GROW];
    __shared__ __align__(16) char GsLo[32 * GROW];
    __shared__ float2 eds[NN];
    __shared__ unsigned adjw[64][33];
    const int b = blockIdx.z, h = blockIdx.y, bh = b * HH + h;
    const int i0 = blockIdx.x * 64;
    const int tid = threadIdx.x, wid = tid >> 5, lane = tid & 31;
    const int g = lane >> 2, t = lane & 3;

    // stage ed/ed2 and adj words for this block
    for (int j = tid; j < NN; j += 128)
        eds[j] = make_float2(ed[bh * NN + j], ed2[bh * NN + j]);
    for (int k = tid; k < 64 * 32; k += 128)
        adjw[k >> 5][k & 31] = adjb[(size_t)(i0 + (k >> 5)) * 32 + (k & 31)];

    const int r0 = i0 + wid * 16 + g;                 // warp's row pair: r0, r0+8
    const float es_0  = es [bh * NN + r0];
    const float es_1  = es [bh * NN + r0 + 8];
    const float es2_0 = es2[bh * NN + r0];
    const float es2_1 = es2[bh * NN + r0 + 8];

    float acc[4][4] = {};
    const uint32_t gsHiA = smem_u32(GsHi), gsLoA = smem_u32(GsLo);
    // ldmatrix lane address offset: matrices {b0 nt0, b1 nt0, b0 nt1, b1 nt1}
    const int d_l  = ((lane >> 4) & 1) * 8 + (lane & 7);
    const int jo_l = ((lane >> 3) & 1) * 8;
    const uint32_t lmoff = (uint32_t)(d_l * GROW + jo_l * 2);

    const __nv_bfloat16* ghb = gthi + (size_t)bh * 32 * NN;
    const __nv_bfloat16* glb = gtlo + (size_t)bh * 32 * NN;

    for (int ck = 0; ck < NN; ck += 128) {
        __syncthreads();
        #pragma unroll
        for (int q = 0; q < 4; ++q) {
            const int idx = tid + q * 128;            // 0..511
            const int d = idx >> 4, c16 = idx & 15;
            const uint4 vh = *(const uint4*)(ghb + (size_t)d * NN + ck + c16 * 8);
            const uint4 vl = *(const uint4*)(glb + (size_t)d * NN + ck + c16 * 8);
            *(uint4*)(GsHi + d * GROW + c16 * 16) = vh;
            *(uint4*)(GsLo + d * GROW + c16 * 16) = vl;
        }
        __syncthreads();
        #pragma unroll
        for (int kk = 0; kk < 128; kk += 16) {
            const int jc = ck + kk;
            // ---- A fragments (W) generated in-register ----
            const unsigned bits0 = adjw[wid * 16 + g][jc >> 5] >> (jc & 31);
            const unsigned bits1 = adjw[wid * 16 + g + 8][jc >> 5] >> (jc & 31);
            const float2 e0 = eds[jc + 2 * t];
            const float2 e1 = eds[jc + 2 * t + 1];
            const float2 e2 = eds[jc + 2 * t + 8];
            const float2 e3 = eds[jc + 2 * t + 9];
            const float w00 = wv(es_0, es2_0, e0, bits0, 2 * t);
            const float w01 = wv(es_0, es2_0, e1, bits0, 2 * t + 1);
            const float w02 = wv(es_0, es2_0, e2, bits0, 2 * t + 8);
            const float w03 = wv(es_0, es2_0, e3, bits0, 2 * t + 9);
            const float w10 = wv(es_1, es2_1, e0, bits1, 2 * t);
            const float w11 = wv(es_1, es2_1, e1, bits1, 2 * t + 1);
            const float w12 = wv(es_1, es2_1, e2, bits1, 2 * t + 8);
            const float w13 = wv(es_1, es2_1, e3, bits1, 2 * t + 9);
            const uint32_t ahi0 = cvt2(w01, w00);
            const uint32_t ahi1 = cvt2(w11, w10);
            const uint32_t ahi2 = cvt2(w03, w02);
            const uint32_t ahi3 = cvt2(w13, w12);
            const uint32_t alo0 = cvt2(w01 - __uint_as_float(ahi0 & 0xFFFF0000u),
                                       w00 - __uint_as_float(ahi0 << 16));
            const uint32_t alo1 = cvt2(w11 - __uint_as_float(ahi1 & 0xFFFF0000u),
                                       w10 - __uint_as_float(ahi1 << 16));
            const uint32_t alo2 = cvt2(w03 - __uint_as_float(ahi2 & 0xFFFF0000u),
                                       w02 - __uint_as_float(ahi2 << 16));
            const uint32_t alo3 = cvt2(w13 - __uint_as_float(ahi3 & 0xFFFF0000u),
                                       w12 - __uint_as_float(ahi3 << 16));
            // ---- B fragments via ldmatrix ----
            uint32_t bh01[4], bh23[4], bl01[4], bl23[4];
            ldm_x4(bh01[0], bh01[1], bh01[2], bh01[3], gsHiA + lmoff + kk * 2);
            ldm_x4(bh23[0], bh23[1], bh23[2], bh23[3], gsHiA + lmoff + kk * 2 + 16 * GROW);
            ldm_x4(bl01[0], bl01[1], bl01[2], bl01[3], gsLoA + lmoff + kk * 2);
            ldm_x4(bl23[0], bl23[1], bl23[2], bl23[3], gsLoA + lmoff + kk * 2 + 16 * GROW);
            // ---- 12 MMAs: Whi*Ghi + Whi*Glo + Wlo*Ghi ----
            mma16816(acc[0], ahi0, ahi1, ahi2, ahi3, bh01[0], bh01[1]);
            mma16816(acc[0], ahi0, ahi1, ahi2, ahi3, bl01[0], bl01[1]);
            mma16816(acc[0], alo0, alo1, alo2, alo3, bh01[0], bh01[1]);
            mma16816(acc[1], ahi0, ahi1, ahi2, ahi3, bh01[2], bh01[3]);
            mma16816(acc[1], ahi0, ahi1, ahi2, ahi3, bl01[2], bl01[3]);
            mma16816(acc[1], alo0, alo1, alo2, alo3, bh01[2], bh01[3]);
            mma16816(acc[2], ahi0, ahi1, ahi2, ahi3, bh23[0], bh23[1]);
            mma16816(acc[2], ahi0, ahi1, ahi2, ahi3, bl23[0], bl23[1]);
            mma16816(acc[2], alo0, alo1, alo2, alo3, bh23[0], bh23[1]);
            mma16816(acc[3], ahi0, ahi1, ahi2, ahi3, bh23[2], bh23[3]);
            mma16816(acc[3], ahi0, ahi1, ahi2, ahi3, bl23[2], bl23[3]);
            mma16816(acc[3], alo0, alo1, alo2, alo3, bh23[2], bh23[3]);
        }
    }
    // epilogue: thread holds D[g][2t..2t+1] and D[g+8][2t..2t+1] per n-tile
    float* op = out + (size_t)(b * NN + r0) * FF + h * 32;
    #pragma unroll
    for (int nt = 0; nt < 4; ++nt) {
        *(float2*)(op + nt * 8 + 2 * t) = make_float2(acc[nt][0], acc[nt][1]);
        *(float2*)(op + (size_t)8 * FF + nt * 8 + 2 * t) = make_float2(acc[nt][2], acc[nt][3]);
    }
}

// ---------------- BatchNorm over batch (B=4) + ReLU (+residual) ----------------
template <bool ADDRES>
__global__ __launch_bounds__(256) void bn_k(const float* __restrict__ y,
                                            const float* __restrict__ gamma,
                                            const float* __restrict__ beta,
                                            const float* __restrict__ resid,
                                            float* __restrict__ out) {
    const int p = blockIdx.x * 256 + threadIdx.x;
    const float v0 = y[p];
    const float v1 = y[NF + p];
    const float v2 = y[2 * NF + p];
    const float v3 = y[3 * NF + p];
    const float mu = 0.25f * (v0 + v1 + v2 + v3);
    const float d0 = v0 - mu, d1 = v1 - mu, d2 = v2 - mu, d3 = v3 - mu;
    const float var = 0.25f * (d0 * d0 + d1 * d1 + d2 * d2 + d3 * d3);
    const float rs = rsqrtf(var + 1e-5f);
    const float ga = gamma[p] * rs;
    const float be = beta[p];
    float o0 = fmaxf(fmaf(ga, d0, be), 0.f);
    float o1 = fmaxf(fmaf(ga, d1, be), 0.f);
    float o2 = fmaxf(fmaf(ga, d2, be), 0.f);
    float o3 = fmaxf(fmaf(ga, d3, be), 0.f);
    if (ADDRES) {
        o0 += resid[p];
        o1 += resid[NF + p];
        o2 += resid[2 * NF + p];
        o3 += resid[3 * NF + p];
    }
    out[p] = o0;
    out[NF + p] = o1;
    out[2 * NF + p] = o2;
    out[3 * NF + p] = o3;
}

// ---------------- launch ----------------
extern "C" void kernel_launch(void* const* d_in, const int* in_sizes, int n_in,
                              void* d_out, int out_size) {
    const float* x  = (const float*)d_in[0];
    const int*  adj = (const int*)  d_in[1];
    const float* W1 = (const float*)d_in[2];
    const float* a1 = (const float*)d_in[3];
    const float* g1 = (const float*)d_in[4];
    const float* b1 = (const float*)d_in[5];
    const float* W2 = (const float*)d_in[6];
    const float* a2 = (const float*)d_in[7];
    const float* g2 = (const float*)d_in[8];
    const float* b2 = (const float*)d_in[9];
    float* out = (float*)d_out;

    static float *pg = nullptr, *patt, *py, *pex, *pden;
    static unsigned* padjb;
    static __nv_bfloat16 *pgthi, *pgtlo;
    if (!pg) {
        cudaGetSymbolAddress((void**)&pg,    g_buf);
        cudaGetSymbolAddress((void**)&patt,  att_buf);
        cudaGetSymbolAddress((void**)&py,    y_buf);
        cudaGetSymbolAddress((void**)&pex,   ex_buf);
        cudaGetSymbolAddress((void**)&pden,  den_buf);
        cudaGetSymbolAddress((void**)&padjb, adjb_buf);
        cudaGetSymbolAddress((void**)&pgthi, gthi_buf);
        cudaGetSymbolAddress((void**)&pgtlo, gtlo_buf);
    }
    const int EXN = BB * HH * NN;
    float* pes  = pex;
    float* pes2 = pex + EXN;
    float* ped  = pex + 2 * EXN;
    float* ped2 = pex + 3 * EXN;

    adjp_k<<<1024, 32>>>(adj, padjb);

    // ---- layer 1 ----
    gemm_nt<<<dim3(4, 64), 256>>>(x, W1, pg);
    srcdst_k<<<512, dim3(32, 8)>>>(pg, a1, pes, pes2, ped, ped2, pden);
    denom_k<<<dim3(4, 8, 4), 512>>>(padjb, pes, pes2, ped, ped2, pden);
    gt_k<<<dim3(8, 8, 4), 256>>>(pg, pden, pgthi, pgtlo);
    attn_k<<<dim3(16, 8, 4), 128>>>(padjb, pes, pes2, ped, ped2, pgthi, pgtlo, patt);
    bn_k<false><<<1024, 256>>>(patt, g1, b1, nullptr, py);

    // ---- layer 2 ----
    gemm_nt<<<dim3(4, 64), 256>>>(py, W2, pg);
    srcdst_k<<<512, dim3(32, 8)>>>(pg, a2, pes, pes2, ped, ped2, pden);
    denom_k<<<dim3(4, 8, 4), 512>>>(padjb, pes, pes2, ped, ped2, pden);
    gt_k<<<dim3(8, 8, 4), 256>>>(pg, pden, pgthi, pgtlo);
    attn_k<<<dim3(16, 8, 4), 128>>>(padjb, pes, pes2, ped, ped2, pgthi, pgtlo, patt);
    bn_k<true><<<1024, 256>>>(patt, g2, b2, x, out);
}

// round 8
// speedup vs baseline: 2.4591x; 1.1276x over previous
#include <cuda_runtime.h>
#include <cuda_bf16.h>
#include <cstdint>

#define BB 4
#define NN 1024
#define FF 256
#define HH 8
#define NF (NN*FF)

// ---------------- scratch (no allocations allowed) ----------------
__device__ float g_buf  [BB*NN*FF];
__device__ float p0_buf [BB*NN*FF];
__device__ float p1_buf [BB*NN*FF];
__device__ float y_buf  [BB*NN*FF];
__device__ float ex_buf [4*BB*HH*NN];   // es, es2, ed, ed2  each [bh][n]
__device__ float den_buf[BB*HH*NN];
__device__ unsigned adjb_buf[NN*32];    // adj bitmask: row i, 32 words over j
__device__ __nv_bfloat16 gthi_buf[BB*HH*32*NN];   // G^T hi  [bh][d][j]
__device__ __nv_bfloat16 gtlo_buf[BB*HH*32*NN];   // G^T lo

// ---------------- f32x2 helpers (sm_100+) ----------------
__device__ __forceinline__ unsigned long long pack2(float a, float b) {
    unsigned long long r;
    asm("mov.b64 %0, {%1, %2};" : "=l"(r) : "f"(a), "f"(b));
    return r;
}
__device__ __forceinline__ void ffma2(unsigned long long& acc,
                                      unsigned long long a, unsigned long long b) {
    asm("fma.rn.f32x2 %0, %1, %2, %0;" : "+l"(acc) : "l"(a), "l"(b));
}
union F4U2 { float4 f; ulonglong2 u; };

// ---------------- mma helpers ----------------
__device__ __forceinline__ uint32_t smem_u32(const void* p) {
    uint32_t a;
    asm("{ .reg .u64 t; cvta.to.shared.u64 t, %1; cvt.u32.u64 %0, t; }" : "=r"(a) : "l"(p));
    return a;
}
__device__ __forceinline__ uint32_t cvt2(float hi, float lo) {
    uint32_t r;
    asm("cvt.rn.bf16x2.f32 %0, %1, %2;" : "=r"(r) : "f"(hi), "f"(lo));
    return r;
}
__device__ __forceinline__ void ldm_x4(uint32_t& r0, uint32_t& r1, uint32_t& r2,
                                       uint32_t& r3, uint32_t addr) {
    asm volatile("ldmatrix.sync.aligned.m8n8.x4.shared.b16 {%0,%1,%2,%3}, [%4];"
                 : "=r"(r0), "=r"(r1), "=r"(r2), "=r"(r3) : "r"(addr));
}
__device__ __forceinline__ void mma16816(float* c, uint32_t a0, uint32_t a1,
                                         uint32_t a2, uint32_t a3,
                                         uint32_t b0, uint32_t b1) {
    asm volatile(
        "mma.sync.aligned.m16n8k16.row.col.f32.bf16.bf16.f32 "
        "{%0,%1,%2,%3}, {%4,%5,%6,%7}, {%8,%9}, {%0,%1,%2,%3};"
        : "+f"(c[0]), "+f"(c[1]), "+f"(c[2]), "+f"(c[3])
        : "r"(a0), "r"(a1), "r"(a2), "r"(a3), "r"(b0), "r"(b1));
}

// ---------------- GEMM: C[m][o] = sum_k A[m][k]*W[o][k] ----------------
__global__ __launch_bounds__(256) void gemm_nt(const float* __restrict__ A,
                                               const float* __restrict__ W,
                                               float* __restrict__ C) {
    __shared__ float As[16][68];
    __shared__ float Bs[16][68];
    const int m0 = blockIdx.y * 64;
    const int o0 = blockIdx.x * 64;
    const int tx = threadIdx.x & 15;
    const int ty = threadIdx.x >> 4;
    unsigned long long acc2[4][2];
    #pragma unroll
    for (int a = 0; a < 4; a++) { acc2[a][0] = 0ull; acc2[a][1] = 0ull; }
    for (int k0 = 0; k0 < 256; k0 += 16) {
        const int c = threadIdx.x & 15;
        const int r = threadIdx.x >> 4;
        #pragma unroll
        for (int rr = 0; rr < 64; rr += 16) {
            As[c][r + rr] = A[(m0 + r + rr) * 256 + k0 + c];
            Bs[c][r + rr] = W[(o0 + r + rr) * 256 + k0 + c];
        }
        __syncthreads();
        #pragma unroll
        for (int kk = 0; kk < 16; kk++) {
            F4U2 a4, b4;
            a4.f = *(const float4*)&As[kk][ty * 4];
            b4.f = *(const float4*)&Bs[kk][tx * 4];
            const unsigned long long ap0 = pack2(a4.f.x, a4.f.x);
            const unsigned long long ap1 = pack2(a4.f.y, a4.f.y);
            const unsigned long long ap2 = pack2(a4.f.z, a4.f.z);
            const unsigned long long ap3 = pack2(a4.f.w, a4.f.w);
            ffma2(acc2[0][0], ap0, b4.u.x); ffma2(acc2[0][1], ap0, b4.u.y);
            ffma2(acc2[1][0], ap1, b4.u.x); ffma2(acc2[1][1], ap1, b4.u.y);
            ffma2(acc2[2][0], ap2, b4.u.x); ffma2(acc2[2][1], ap2, b4.u.y);
            ffma2(acc2[3][0], ap3, b4.u.x); ffma2(acc2[3][1], ap3, b4.u.y);
        }
        __syncthreads();
    }
    #pragma unroll
    for (int a = 0; a < 4; a++) {
        F4U2 o;
        o.u.x = acc2[a][0];
        o.u.y = acc2[a][1];
        *(float4*)&C[(m0 + ty * 4 + a) * 256 + o0 + tx * 4] = o.f;
    }
}

// ---------------- adj -> bitmask ----------------
__global__ __launch_bounds__(32) void adjp_k(const int* __restrict__ adj,
                                             unsigned* __restrict__ adjb) {
    const int i = blockIdx.x, lane = threadIdx.x;
    #pragma unroll 4
    for (int w = 0; w < 32; ++w) {
        int v = adj[i * 1024 + w * 32 + lane];
        unsigned m = __ballot_sync(0xFFFFFFFFu, v != 0);
        if (lane == w) adjb[i * 32 + w] = m;
    }
}

// ---------------- src/dst projections -> exp tables; zero den ----------------
__global__ __launch_bounds__(256) void srcdst_k(const float* __restrict__ g,
                                                const float* __restrict__ a,
                                                float* __restrict__ es,
                                                float* __restrict__ es2,
                                                float* __restrict__ ed,
                                                float* __restrict__ ed2,
                                                float* __restrict__ den) {
    const int gtid = blockIdx.x * 256 + threadIdx.y * 32 + threadIdx.x;
    if (gtid < BB * HH * NN) den[gtid] = 0.f;
    const int row  = blockIdx.x * 8 + threadIdx.y;   // b*NN+n
    const int b = row >> 10, n = row & 1023;
    const int lane = threadIdx.x;
    const float as = a[lane];
    const float ad = a[32 + lane];
    const float* gr = g + row * 256;
    #pragma unroll
    for (int h = 0; h < HH; h++) {
        float v = gr[h * 32 + lane];
        float s = v * as;
        float d = v * ad;
        #pragma unroll
        for (int off = 16; off; off >>= 1) {
            s += __shfl_down_sync(0xFFFFFFFFu, s, off);
            d += __shfl_down_sync(0xFFFFFFFFu, d, off);
        }
        if (lane == 0) {
            const int idx = (b * HH + h) * NN + n;
            es [idx] = __expf(s);
            es2[idx] = __expf(0.2f * s);
            ed [idx] = __expf(d);
            ed2[idx] = __expf(0.2f * d);
        }
    }
}

// ---------------- den[bh][j] += sum_{i chunk} adj * w(i,j)  (no exp) ----------------
// grid (16 i-chunks of 64, HH, BB), 512 threads, 2 j per thread
__global__ __launch_bounds__(512) void denom_k(const unsigned* __restrict__ adjb,
                                               const float* __restrict__ es,
                                               const float* __restrict__ es2,
                                               const float* __restrict__ ed,
                                               const float* __restrict__ ed2,
                                               float* __restrict__ den) {
    __shared__ float ess[64], ess2[64];
    const int b = blockIdx.z, h = blockIdx.y, bh = b * HH + h;
    const int ic = blockIdx.x * 64;
    const int tid = threadIdx.x;
    if (tid < 64) ess[tid] = es[bh * NN + ic + tid];
    else if (tid < 128) ess2[tid - 64] = es2[bh * NN + ic + tid - 64];
    __syncthreads();
    const int j0 = tid, j1 = tid + 512;
    const float edj0 = ed[bh * NN + j0], ed2j0 = ed2[bh * NN + j0];
    const float edj1 = ed[bh * NN + j1], ed2j1 = ed2[bh * NN + j1];
    const int w0i = j0 >> 5, w1i = j1 >> 5, s0 = j0 & 31, s1 = j1 & 31;
    float a0 = 0.f, a1 = 0.f;
    #pragma unroll 4
    for (int i = 0; i < 64; ++i) {
        const unsigned* row = adjb + (size_t)(ic + i) * 32;
        const unsigned word0 = row[w0i];
        const unsigned word1 = row[w1i];
        const float esi = ess[i], es2i = ess2[i];
        float p = esi * edj0, p2 = es2i * ed2j0;
        float v = (p >= 1.f) ? p : p2;
        if ((word0 >> s0) & 1u) a0 += v;
        p = esi * edj1; p2 = es2i * ed2j1;
        v = (p >= 1.f) ? p : p2;
        if ((word1 >> s1) & 1u) a1 += v;
    }
    atomicAdd(&den[bh * NN + j0], a0);
    atomicAdd(&den[bh * NN + j1], a1);
}

// ---------------- gt: gs = g/den, transposed to [bh][d][j], split bf16 hi/lo ----------------
__global__ __launch_bounds__(256) void gt_k(const float* __restrict__ g,
                                            const float* __restrict__ den,
                                            __nv_bfloat16* __restrict__ gthi,
                                            __nv_bfloat16* __restrict__ gtlo) {
    __shared__ uint32_t sm[128][33];
    const int b = blockIdx.z, h = blockIdx.y, jc = blockIdx.x * 128;
    const int tid = threadIdx.x;
    const int jr0 = tid >> 3, c4 = (tid & 7) * 4;
    #pragma unroll
    for (int p = 0; p < 4; ++p) {
        const int jr = jr0 + p * 32;
        const int j = jc + jr;
        const float r = 1.0f / den[(b * HH + h) * NN + j];
        float4 v = *(const float4*)&g[(size_t)(b * NN + j) * FF + h * 32 + c4];
        float vs[4] = {v.x * r, v.y * r, v.z * r, v.w * r};
        #pragma unroll
        for (int q = 0; q < 4; ++q) {
            __nv_bfloat16 hi = __float2bfloat16(vs[q]);
            __nv_bfloat16 lo = __float2bfloat16(vs[q] - __bfloat162float(hi));
            sm[jr][c4 + q] = (uint32_t)__bfloat16_as_ushort(hi)
                           | ((uint32_t)__bfloat16_as_ushort(lo) << 16);
        }
    }
    __syncthreads();
    const int d = tid >> 3, j0 = (tid & 7) * 16;
    __align__(16) unsigned short his[16];
    __align__(16) unsigned short los[16];
    #pragma unroll
    for (int k = 0; k < 16; ++k) {
        uint32_t v = sm[j0 + k][d];
        his[k] = (unsigned short)(v & 0xFFFF);
        los[k] = (unsigned short)(v >> 16);
    }
    const size_t base = (size_t)((b * HH + h) * 32 + d) * NN + jc + j0;
    *(uint4*)&gthi[base]     = ((uint4*)his)[0];
    *(uint4*)&gthi[base + 8] = ((uint4*)his)[1];
    *(uint4*)&gtlo[base]     = ((uint4*)los)[0];
    *(uint4*)&gtlo[base + 8] = ((uint4*)los)[1];
}

// ---------------- attention via mma.sync bf16 (hi/lo 3-term), j-split x2 ----------------
// block = 4 warps x 16 i = 64 i rows, one (b, h, j-half). grid (16, 16, 4).
#define GROW 272   // 128 bf16 = 256B + 16B pad (conflict-free ldmatrix)

__device__ __forceinline__ float wv(float esr, float es2r, float2 e,
                                    unsigned bits, int c) {
    const float p = esr * e.x, p2 = es2r * e.y;
    const float v = (p >= 1.0f) ? p : p2;
    return ((bits >> c) & 1u) ? v : 0.0f;
}

__global__ __launch_bounds__(128) void attn_k(const unsigned* __restrict__ adjb,
                                              const float* __restrict__ es,
                                              const float* __restrict__ es2,
                                              const float* __restrict__ ed,
                                              const float* __restrict__ ed2,
                                              const __nv_bfloat16* __restrict__ gthi,
                                              const __nv_bfloat16* __restrict__ gtlo,
                                              float* __restrict__ part0,
                                              float* __restrict__ part1) {
    __shared__ __align__(16) char GsHi[32 * GROW];
    __shared__ __align__(16) char GsLo[32 * GROW];
    __shared__ float2 eds[NN / 2];
    __shared__ unsigned adjw[64][17];
    const int b = blockIdx.z;
    const int h = blockIdx.y & 7, jh = blockIdx.y >> 3;
    const int bh = b * HH + h;
    const int jbase = jh * (NN / 2);
    const int i0 = blockIdx.x * 64;
    const int tid = threadIdx.x, wid = tid >> 5, lane = tid & 31;
    const int g = lane >> 2, t = lane & 3;

    // stage ed/ed2 (this j-half) and adj words for this block
    for (int j = tid; j < NN / 2; j += 128)
        eds[j] = make_float2(ed[bh * NN + jbase + j], ed2[bh * NN + jbase + j]);
    for (int k = tid; k < 64 * 16; k += 128)
        adjw[k >> 4][k & 15] = adjb[(size_t)(i0 + (k >> 4)) * 32 + jh * 16 + (k & 15)];

    const int r0 = i0 + wid * 16 + g;                 // warp's row pair: r0, r0+8
    const float es_0  = es [bh * NN + r0];
    const float es_1  = es [bh * NN + r0 + 8];
    const float es2_0 = es2[bh * NN + r0];
    const float es2_1 = es2[bh * NN + r0 + 8];

    float acc[4][4] = {};
    const uint32_t gsHiA = smem_u32(GsHi), gsLoA = smem_u32(GsLo);
    const int d_l  = ((lane >> 4) & 1) * 8 + (lane & 7);
    const int jo_l = ((lane >> 3) & 1) * 8;
    const uint32_t lmoff = (uint32_t)(d_l * GROW + jo_l * 2);

    const __nv_bfloat16* ghb = gthi + (size_t)bh * 32 * NN + jbase;
    const __nv_bfloat16* glb = gtlo + (size_t)bh * 32 * NN + jbase;

    for (int ck = 0; ck < NN / 2; ck += 128) {
        __syncthreads();
        #pragma unroll
        for (int q = 0; q < 4; ++q) {
            const int idx = tid + q * 128;            // 0..511
            const int d = idx >> 4, c16 = idx & 15;
            const uint4 vh = *(const uint4*)(ghb + (size_t)d * NN + ck + c16 * 8);
            const uint4 vl = *(const uint4*)(glb + (size_t)d * NN + ck + c16 * 8);
            *(uint4*)(GsHi + d * GROW + c16 * 16) = vh;
            *(uint4*)(GsLo + d * GROW + c16 * 16) = vl;
        }
        __syncthreads();
        #pragma unroll
        for (int kk = 0; kk < 128; kk += 16) {
            const int jc = ck + kk;                   // local j within half
            const unsigned bits0 = adjw[wid * 16 + g][jc >> 5] >> (jc & 31);
            const unsigned bits1 = adjw[wid * 16 + g + 8][jc >> 5] >> (jc & 31);
            const float2 e0 = eds[jc + 2 * t];
            const float2 e1 = eds[jc + 2 * t + 1];
            const float2 e2 = eds[jc + 2 * t + 8];
            const float2 e3 = eds[jc + 2 * t + 9];
            const float w00 = wv(es_0, es2_0, e0, bits0, 2 * t);
            const float w01 = wv(es_0, es2_0, e1, bits0, 2 * t + 1);
            const float w02 = wv(es_0, es2_0, e2, bits0, 2 * t + 8);
            const float w03 = wv(es_0, es2_0, e3, bits0, 2 * t + 9);
            const float w10 = wv(es_1, es2_1, e0, bits1, 2 * t);
            const float w11 = wv(es_1, es2_1, e1, bits1, 2 * t + 1);
            const float w12 = wv(es_1, es2_1, e2, bits1, 2 * t + 8);
            const float w13 = wv(es_1, es2_1, e3, bits1, 2 * t + 9);
            const uint32_t ahi0 = cvt2(w01, w00);
            const uint32_t ahi1 = cvt2(w11, w10);
            const uint32_t ahi2 = cvt2(w03, w02);
            const uint32_t ahi3 = cvt2(w13, w12);
            const uint32_t alo0 = cvt2(w01 - __uint_as_float(ahi0 & 0xFFFF0000u),
                                       w00 - __uint_as_float(ahi0 << 16));
            const uint32_t alo1 = cvt2(w11 - __uint_as_float(ahi1 & 0xFFFF0000u),
                                       w10 - __uint_as_float(ahi1 << 16));
            const uint32_t alo2 = cvt2(w03 - __uint_as_float(ahi2 & 0xFFFF0000u),
                                       w02 - __uint_as_float(ahi2 << 16));
            const uint32_t alo3 = cvt2(w13 - __uint_as_float(ahi3 & 0xFFFF0000u),
                                       w12 - __uint_as_float(ahi3 << 16));
            uint32_t bh01[4], bh23[4], bl01[4], bl23[4];
            ldm_x4(bh01[0], bh01[1], bh01[2], bh01[3], gsHiA + lmoff + kk * 2);
            ldm_x4(bh23[0], bh23[1], bh23[2], bh23[3], gsHiA + lmoff + kk * 2 + 16 * GROW);
            ldm_x4(bl01[0], bl01[1], bl01[2], bl01[3], gsLoA + lmoff + kk * 2);
            ldm_x4(bl23[0], bl23[1], bl23[2], bl23[3], gsLoA + lmoff + kk * 2 + 16 * GROW);
            mma16816(acc[0], ahi0, ahi1, ahi2, ahi3, bh01[0], bh01[1]);
            mma16816(acc[0], ahi0, ahi1, ahi2, ahi3, bl01[0], bl01[1]);
            mma16816(acc[0], alo0, alo1, alo2, alo3, bh01[0], bh01[1]);
            mma16816(acc[1], ahi0, ahi1, ahi2, ahi3, bh01[2], bh01[3]);
            mma16816(acc[1], ahi0, ahi1, ahi2, ahi3, bl01[2], bl01[3]);
            mma16816(acc[1], alo0, alo1, alo2, alo3, bh01[2], bh01[3]);
            mma16816(acc[2], ahi0, ahi1, ahi2, ahi3, bh23[0], bh23[1]);
            mma16816(acc[2], ahi0, ahi1, ahi2, ahi3, bl23[0], bl23[1]);
            mma16816(acc[2], alo0, alo1, alo2, alo3, bh23[0], bh23[1]);
            mma16816(acc[3], ahi0, ahi1, ahi2, ahi3, bh23[2], bh23[3]);
            mma16816(acc[3], ahi0, ahi1, ahi2, ahi3, bl23[2], bl23[3]);
            mma16816(acc[3], alo0, alo1, alo2, alo3, bh23[2], bh23[3]);
        }
    }
    float* po = (jh ? part1 : part0) + (size_t)(b * NN + r0) * FF + h * 32;
    #pragma unroll
    for (int nt = 0; nt < 4; ++nt) {
        *(float2*)(po + nt * 8 + 2 * t) = make_float2(acc[nt][0], acc[nt][1]);
        *(float2*)(po + (size_t)8 * FF + nt * 8 + 2 * t) = make_float2(acc[nt][2], acc[nt][3]);
    }
}

// ---------------- BatchNorm over batch (B=4) + ReLU (+residual); sums 2 partials ----------------
template <bool ADDRES>
__global__ __launch_bounds__(256) void bn_k(const float* __restrict__ y0,
                                            const float* __restrict__ y1,
                                            const float* __restrict__ gamma,
                                            const float* __restrict__ beta,
                                            const float* __restrict__ resid,
                                            float* __restrict__ out) {
    const int p = blockIdx.x * 256 + threadIdx.x;
    const float v0 = y0[p]          + y1[p];
    const float v1 = y0[NF + p]     + y1[NF + p];
    const float v2 = y0[2 * NF + p] + y1[2 * NF + p];
    const float v3 = y0[3 * NF + p] + y1[3 * NF + p];
    const float mu = 0.25f * (v0 + v1 + v2 + v3);
    const float d0 = v0 - mu, d1 = v1 - mu, d2 = v2 - mu, d3 = v3 - mu;
    const float var = 0.25f * (d0 * d0 + d1 * d1 + d2 * d2 + d3 * d3);
    const float rs = rsqrtf(var + 1e-5f);
    const float ga = gamma[p] * rs;
    const float be = beta[p];
    float o0 = fmaxf(fmaf(ga, d0, be), 0.f);
    float o1 = fmaxf(fmaf(ga, d1, be), 0.f);
    float o2 = fmaxf(fmaf(ga, d2, be), 0.f);
    float o3 = fmaxf(fmaf(ga, d3, be), 0.f);
    if (ADDRES) {
        o0 += resid[p];
        o1 += resid[NF + p];
        o2 += resid[2 * NF + p];
        o3 += resid[3 * NF + p];
    }
    out[p] = o0;
    out[NF + p] = o1;
    out[2 * NF + p] = o2;
    out[3 * NF + p] = o3;
}

// ---------------- launch ----------------
extern "C" void kernel_launch(void* const* d_in, const int* in_sizes, int n_in,
                              void* d_out, int out_size) {
    const float* x  = (const float*)d_in[0];
    const int*  adj = (const int*)  d_in[1];
    const float* W1 = (const float*)d_in[2];
    const float* a1 = (const float*)d_in[3];
    const float* g1 = (const float*)d_in[4];
    const float* b1 = (const float*)d_in[5];
    const float* W2 = (const float*)d_in[6];
    const float* a2 = (const float*)d_in[7];
    const float* g2 = (const float*)d_in[8];
    const float* b2 = (const float*)d_in[9];
    float* out = (float*)d_out;

    static float *pg = nullptr, *pp0, *pp1, *py, *pex, *pden;
    static unsigned* padjb;
    static __nv_bfloat16 *pgthi, *pgtlo;
    if (!pg) {
        cudaGetSymbolAddress((void**)&pg,    g_buf);
        cudaGetSymbolAddress((void**)&pp0,   p0_buf);
        cudaGetSymbolAddress((void**)&pp1,   p1_buf);
        cudaGetSymbolAddress((void**)&py,    y_buf);
        cudaGetSymbolAddress((void**)&pex,   ex_buf);
        cudaGetSymbolAddress((void**)&pden,  den_buf);
        cudaGetSymbolAddress((void**)&padjb, adjb_buf);
        cudaGetSymbolAddress((void**)&pgthi, gthi_buf);
        cudaGetSymbolAddress((void**)&pgtlo, gtlo_buf);
    }
    const int EXN = BB * HH * NN;
    float* pes  = pex;
    float* pes2 = pex + EXN;
    float* ped  = pex + 2 * EXN;
    float* ped2 = pex + 3 * EXN;

    adjp_k<<<1024, 32>>>(adj, padjb);

    // ---- layer 1 ----
    gemm_nt<<<dim3(4, 64), 256>>>(x, W1, pg);
    srcdst_k<<<512, dim3(32, 8)>>>(pg, a1, pes, pes2, ped, ped2, pden);
    denom_k<<<dim3(16, 8, 4), 512>>>(padjb, pes, pes2, ped, ped2, pden);
    gt_k<<<dim3(8, 8, 4), 256>>>(pg, pden, pgthi, pgtlo);
    attn_k<<<dim3(16, 16, 4), 128>>>(padjb, pes, pes2, ped, ped2, pgthi, pgtlo, pp0, pp1);
    bn_k<false><<<1024, 256>>>(pp0, pp1, g1, b1, nullptr, py);

    // ---- layer 2 ----
    gemm_nt<<<dim3(4, 64), 256>>>(py, W2, pg);
    srcdst_k<<<512, dim3(32, 8)>>>(pg, a2, pes, pes2, ped, ped2, pden);
    denom_k<<<dim3(16, 8, 4), 512>>>(padjb, pes, pes2, ped, ped2, pden);
    gt_k<<<dim3(8, 8, 4), 256>>>(pg, pden, pgthi, pgtlo);
    attn_k<<<dim3(16, 16, 4), 128>>>(padjb, pes, pes2, ped, ped2, pgthi, pgtlo, pp0, pp1);
    bn_k<true><<<1024, 256>>>(pp0, pp1, g2, b2, x, out);
}